// round 13
// baseline (speedup 1.0000x reference)
#include <cuda_runtime.h>
#include <cuda_bf16.h>
#include <math.h>
#include <stdint.h>

#define BB 4
#define TT 1024
#define DD 1024
#define HH 16
#define DFF 4096
#define RR 8
#define BT (BB*TT)
#define BTD (BB*TT*DD)
#define SZP (512*1024)
#define SZF 2097152

// ---------------- device scratch ----------------
__device__ float g_cur[BTD];
__device__ float g_xo[BTD];
__device__ float g_v[BTD];
__device__ uint32_t g_qh[BT*512], g_ql[BT*512];
__device__ uint32_t g_kh[BT*512], g_kl[BT*512];
__device__ uint32_t g_vh[BB*HH*512*64], g_vl[BB*HH*512*64];
__device__ uint32_t g_oh[BT*512], g_ol[BT*512];
__device__ uint32_t g_normh[BT*512], g_norml[BT*512];
__device__ uint32_t g_midh[BT*2048], g_midl[BT*2048];
__device__ uint32_t g_wph[4*SZP + 2*SZF], g_wpl[4*SZP + 2*SZF];
__device__ float g_part[BB*32*DD];
__device__ float g_ctxm[BB*DD];
__device__ float g_ctx[BB*DD];
__device__ float g_rt[BB*80];
__device__ float g_h1[BB*256];
__device__ float g_gate[BB];
__device__ float g_gm;
__device__ int   g_idx[3];

__device__ __forceinline__ float geluf(float x){
    return 0.5f*x*(1.0f+erff(x*0.7071067811865476f));
}
__device__ __forceinline__ void split2(float x, float y, uint32_t &hi, uint32_t &lo){
    __nv_bfloat16 xh = __float2bfloat16_rn(x);
    __nv_bfloat16 yh = __float2bfloat16_rn(y);
    __nv_bfloat162 h; h.x = xh; h.y = yh;
    __nv_bfloat162 l; l.x = __float2bfloat16_rn(x - __bfloat162float(xh));
    l.y = __float2bfloat16_rn(y - __bfloat162float(yh));
    hi = *(uint32_t*)&h; lo = *(uint32_t*)&l;
}
__device__ __forceinline__ void mma_bf16(float* c, uint32_t a0, uint32_t a1, uint32_t a2, uint32_t a3,
                                         uint32_t b0, uint32_t b1){
    asm volatile("mma.sync.aligned.m16n8k16.row.col.f32.bf16.bf16.f32 "
        "{%0,%1,%2,%3},{%4,%5,%6,%7},{%8,%9},{%0,%1,%2,%3};"
        : "+f"(c[0]), "+f"(c[1]), "+f"(c[2]), "+f"(c[3])
        : "r"(a0), "r"(a1), "r"(a2), "r"(a3), "r"(b0), "r"(b1));
}
#define MMA3(accp, AH, AL, BH0, BH1, BL0, BL1) \
    mma_bf16(accp, AH[0],AH[1],AH[2],AH[3], BH0, BH1); \
    mma_bf16(accp, AH[0],AH[1],AH[2],AH[3], BL0, BL1); \
    mma_bf16(accp, AL[0],AL[1],AL[2],AL[3], BH0, BH1);

__device__ __forceinline__ void cpa16(void* dst, const void* src){
    uint32_t d = (uint32_t)__cvta_generic_to_shared(dst);
    asm volatile("cp.async.cg.shared.global [%0], [%1], 16;" :: "r"(d), "l"(src));
}
#define CP_COMMIT() asm volatile("cp.async.commit_group;")

// ---------------- small kernels ----------------
__global__ void k_meanT_part(const float* __restrict__ in){
    int b = blockIdx.x, c = blockIdx.y;
    int t0 = c*32;
    for(int d = threadIdx.x; d < DD; d += 256){
        float s = 0.f;
        for(int t = t0; t < t0+32; t++) s += in[((size_t)(b*TT+t))*DD + d];
        g_part[(size_t)(b*32+c)*DD + d] = s;
    }
}
__global__ void k_meanT_reduce(){
    int b = blockIdx.x;
    for(int d = threadIdx.x; d < DD; d += 256){
        float s = 0.f;
        for(int c = 0; c < 32; c++) s += g_part[(size_t)(b*32+c)*DD + d];
        g_ctxm[b*DD + d] = s*(1.0f/TT);
    }
}
__global__ void k_ctx(const float* __restrict__ W, const float* __restrict__ bias){
    int b = blockIdx.x; int n0 = blockIdx.y*32;
    int lane = threadIdx.x & 31, q = threadIdx.x >> 5;
    const float* xv = &g_ctxm[b*DD];
    float s = 0.f;
    int k0 = q*256;
    for(int k = k0; k < k0+256; k++) s += xv[k]*W[(size_t)k*DD + n0 + lane];
    __shared__ float red[4][32];
    red[q][lane] = s; __syncthreads();
    if(q == 0)
        g_ctx[b*DD + n0 + lane] = red[0][lane]+red[1][lane]+red[2][lane]+red[3][lane] + bias[n0+lane];
}
__global__ void __launch_bounds__(128) k_route1(const float* __restrict__ warp_w,
        const float* __restrict__ summaries, const float* __restrict__ gate_w){
    int b = blockIdx.x, o = blockIdx.y;
    int tid = threadIdx.x;
    const float* xv = &g_ctx[b*DD];
    float s = 0.f;
    if(o < 64){
        for(int k = tid; k < DD; k += 128) s += xv[k]*warp_w[(size_t)k*64 + o];
    } else if(o < 72){
        const float* sr = summaries + (size_t)(o-64)*DD;
        for(int k = tid; k < DD; k += 128) s += xv[k]*sr[k];
    } else {
        for(int k = tid; k < DD; k += 128) s += xv[k]*gate_w[k*RR + (o-72)];
    }
    __shared__ float red[128];
    red[tid] = s; __syncthreads();
    for(int off = 64; off >= 1; off >>= 1){
        if(tid < off) red[tid] += red[tid+off];
        __syncthreads();
    }
    if(tid == 0) g_rt[b*80 + o] = red[0];
}
__global__ void k_route2(const float* __restrict__ base_adj,
                         const float* __restrict__ warp_b, const float* __restrict__ gate_b,
                         float* __restrict__ out_gs, float* __restrict__ out_adj,
                         float* __restrict__ out_mh){
    __shared__ float s_gs[BB][RR];
    int tid = threadIdx.x;
    if(tid < 32){
        int b = tid/8, i = tid%8;
        float v[8]; float mx = -1e30f;
        for(int j = 0; j < 8; j++){
            v[j] = base_adj[i*8+j] + (g_rt[b*80 + i*8 + j] + warp_b[i*8+j])*0.1f;
            mx = fmaxf(mx, v[j]);
        }
        float sum = 0.f;
        for(int j = 0; j < 8; j++){ v[j] = expf(v[j]-mx); sum += v[j]; }
        float inv = 1.0f/sum;
        float boost = 0.f;
        for(int j = 0; j < 8; j++){
            float a = v[j]*inv;
            out_adj[(b*8+i)*8 + j] = a;
            boost += a*g_rt[b*80 + 64 + j];
        }
        float gl = g_rt[b*80 + 72 + i] + gate_b[i];
        float gs = 1.0f/(1.0f+expf(-(gl+boost)*0.5f));
        out_gs[b*8+i] = gs;
        s_gs[b][i] = gs;
    }
    __syncthreads();
    if(tid == 0){
        float m[RR];
        for(int r = 0; r < 8; r++) m[r] = 0.25f*(s_gs[0][r]+s_gs[1][r]+s_gs[2][r]+s_gs[3][r]);
        for(int h = 0; h < 3; h++){
            int best = 0; float bv = -1e30f;
            for(int r = 0; r < 8; r++) if(m[r] > bv){ bv = m[r]; best = r; }
            g_idx[h] = best; m[best] = -1e30f;
        }
        out_mh[0] = 3.0f;
    }
}
__global__ void __launch_bounds__(256) k_g1(const float* __restrict__ g1_w, const float* __restrict__ g1_b, int hop){
    int room = g_idx[hop];
    int b = blockIdx.x;
    int tid = threadIdx.x;
    int n = blockIdx.y*16 + (tid & 15);
    int slice = tid >> 4;
    const float* W = g1_w + (size_t)room*DD*256;
    const float* xv = &g_ctxm[b*DD];
    float s = 0.f;
    int k0 = slice*64;
    for(int k = k0; k < k0+64; k++) s += xv[k]*W[(size_t)k*256 + n];
    __shared__ float red[256];
    red[tid] = s; __syncthreads();
    if(tid < 16){
        float tot = 0.f;
        for(int sl = 0; sl < 16; sl++) tot += red[tid + 16*sl];
        int nn = blockIdx.y*16 + tid;
        g_h1[b*256 + nn] = geluf(tot + g1_b[room*256 + nn]);
    }
}
__global__ void k_g2(const float* __restrict__ g2_w, const float* __restrict__ g2_b, int hop){
    int room = g_idx[hop];
    __shared__ float red[256];
    int tid = threadIdx.x;
    int b = tid/64, lane = tid%64;
    const float* W = g2_w + room*256;
    float s = 0.f;
    for(int k = lane; k < 256; k += 64) s += g_h1[b*256 + k]*W[k];
    red[tid] = s; __syncthreads();
    for(int off = 32; off >= 1; off >>= 1){
        if(lane < off) red[tid] += red[tid+off];
        __syncthreads();
    }
    if(lane == 0){
        float gate = 1.0f/(1.0f+expf(-(red[tid]+g2_b[room])));
        g_gate[b] = gate;
    }
    __syncthreads();
    if(tid == 0) g_gm = 0.25f*(g_gate[0]+g_gate[1]+g_gate[2]+g_gate[3]);
}

// weight pre-pack (single weight): vertical k-pairs, layout [K/2][N]
__global__ void k_packw(const float* __restrict__ Wb, uint32_t* __restrict__ oh, uint32_t* __restrict__ ol,
                        int N, int hop, long wstr){
    int room = g_idx[hop];
    const float* W = Wb + (size_t)room*wstr;
    int i = blockIdx.x*256 + threadIdx.x;
    int k2 = i / N, n = i % N;
    float a = W[(size_t)(2*k2)*N + n];
    float b = W[(size_t)(2*k2+1)*N + n];
    uint32_t hh, ll; split2(a, b, hh, ll);
    oh[i] = hh; ol[i] = ll;
}
// merged pack for the 4 DxD weights: z selects weight
__global__ void k_packw4(const float* __restrict__ w0, const float* __restrict__ w1,
                         const float* __restrict__ w2, const float* __restrict__ w3,
                         uint32_t* __restrict__ oh, uint32_t* __restrict__ ol, int hop){
    int room = g_idx[hop];
    int z = blockIdx.z;
    const float* Wb = (z==0) ? w0 : (z==1) ? w1 : (z==2) ? w2 : w3;
    const float* W = Wb + (size_t)room*DD*DD;
    int i = blockIdx.x*256 + threadIdx.x;
    int k2 = i / DD, n = i % DD;
    float a = W[(size_t)(2*k2)*DD + n];
    float b = W[(size_t)(2*k2+1)*DD + n];
    uint32_t hh, ll; split2(a, b, hh, ll);
    oh[(size_t)z*SZP + i] = hh; ol[(size_t)z*SZP + i] = ll;
}

// V pre-split into flash tile layout
__global__ void __launch_bounds__(256) k_vsplit(const float* __restrict__ v){
    int p = blockIdx.x;
    int t0 = 2*p;
    int b = t0 >> 10;
    int k2g = (t0 & (TT-1)) >> 1;
    int c = threadIdx.x*4;
    int h = c >> 6, dh = c & 63;
    float4 x0 = *(const float4*)(v + (size_t)t0*DD + c);
    float4 x1 = *(const float4*)(v + (size_t)(t0+1)*DD + c);
    const float* r0 = (const float*)&x0;
    const float* r1 = (const float*)&x1;
    uint32_t hh[4], ll[4];
    #pragma unroll
    for(int j = 0; j < 4; j++) split2(r0[j], r1[j], hh[j], ll[j]);
    size_t o = ((size_t)(b*HH + h)*512 + k2g)*64 + dh;
    *(uint4*)(g_vh + o) = make_uint4(hh[0],hh[1],hh[2],hh[3]);
    *(uint4*)(g_vl + o) = make_uint4(ll[0],ll[1],ll[2],ll[3]);
}

// layernorm -> split bf16 planes
__global__ void __launch_bounds__(256) k_ln2(const float* __restrict__ in,
                     const float* __restrict__ gb, const float* __restrict__ bb,
                     int hop, const float* __restrict__ gate,
                     uint32_t* __restrict__ oh, uint32_t* __restrict__ ol){
    int row = blockIdx.x; int b = row >> 10;
    int room = g_idx[hop];
    float sc = gate ? gate[b] : 1.0f;
    float4 v = ((const float4*)(in + (size_t)row*DD))[threadIdx.x];
    v.x *= sc; v.y *= sc; v.z *= sc; v.w *= sc;
    __shared__ float rs[256], rq[256];
    rs[threadIdx.x] = v.x+v.y+v.z+v.w;
    rq[threadIdx.x] = v.x*v.x+v.y*v.y+v.z*v.z+v.w*v.w;
    __syncthreads();
    for(int off = 128; off >= 1; off >>= 1){
        if(threadIdx.x < off){ rs[threadIdx.x] += rs[threadIdx.x+off]; rq[threadIdx.x] += rq[threadIdx.x+off]; }
        __syncthreads();
    }
    float mean = rs[0]*(1.0f/DD);
    float var  = rq[0]*(1.0f/DD) - mean*mean;
    float inv  = rsqrtf(var + 1e-5f);
    float4 g4 = ((const float4*)(gb + (size_t)room*DD))[threadIdx.x];
    float4 b4 = ((const float4*)(bb + (size_t)room*DD))[threadIdx.x];
    float o0 = (v.x-mean)*inv*g4.x + b4.x;
    float o1 = (v.y-mean)*inv*g4.y + b4.y;
    float o2 = (v.z-mean)*inv*g4.z + b4.z;
    float o3 = (v.w-mean)*inv*g4.w + b4.w;
    uint32_t h0,l0,h1,l1;
    split2(o0,o1,h0,l0); split2(o2,o3,h1,l1);
    size_t w = (size_t)row*512 + threadIdx.x*2;
    *(uint2*)&oh[w] = make_uint2(h0,h1);
    *(uint2*)&ol[w] = make_uint2(l0,l1);
}

// ---------------- GEMM core: 256x128 tile, BK=32, 3-stage ring, 512 thr ----------------
// words: sAh[3][256][20] (16B-aligned rows, conflict-free), sBh[3][16][136] (conflict-free)
#define SA_OFF(s,r,c) ((s)*5120 + (r)*20 + (c))
#define SB_OFF(s,k,c) ((s)*2176 + (k)*136 + (c))
#define DSMEM_BYTES ((15360*2 + 6528*2)*4)

__device__ __forceinline__ void gemm_core(
        const uint32_t* __restrict__ Ah, const uint32_t* __restrict__ Al,
        const uint32_t* __restrict__ Wh, const uint32_t* __restrict__ Wl,
        int N, int K, int bm, int bn,
        uint32_t* sAh, uint32_t* sAl, uint32_t* sBh, uint32_t* sBl,
        float acc[2][8][4], int tid, int wm, int wn, int g, int t){
    int halfK = K >> 1;
    int nC = K >> 5;
    int arA = tid>>1, acA = (tid&1)*8;      // 256 rows, 8 words each (2 cpa16)
    int brA = tid>>5, bcA = (tid&31)*4;     // 16 k2 rows x 128 words
    const uint32_t* AhS = Ah + (size_t)(bm*256 + arA)*halfK + acA;
    const uint32_t* AlS = Al + (size_t)(bm*256 + arA)*halfK + acA;
    const uint32_t* WhS = Wh + (size_t)brA*N + bn*128 + bcA;
    const uint32_t* WlS = Wl + (size_t)brA*N + bn*128 + bcA;

    #pragma unroll
    for(int s = 0; s < 2; s++){
        if(s < nC){
            int k0w = s*16;
            cpa16(sAh + SA_OFF(s,arA,acA),   AhS + k0w);
            cpa16(sAh + SA_OFF(s,arA,acA+4), AhS + k0w + 4);
            cpa16(sAl + SA_OFF(s,arA,acA),   AlS + k0w);
            cpa16(sAl + SA_OFF(s,arA,acA+4), AlS + k0w + 4);
            cpa16(sBh + SB_OFF(s,brA,bcA), WhS + (size_t)k0w*N);
            cpa16(sBl + SB_OFF(s,brA,bcA), WlS + (size_t)k0w*N);
            CP_COMMIT();
        }
    }
    for(int c = 0; c < nC; c++){
        if(c+1 < nC) asm volatile("cp.async.wait_group 1;");
        else         asm volatile("cp.async.wait_group 0;");
        __syncthreads();
        if(c+2 < nC){
            int s = (c+2)%3;
            int k0w = (c+2)*16;
            cpa16(sAh + SA_OFF(s,arA,acA),   AhS + k0w);
            cpa16(sAh + SA_OFF(s,arA,acA+4), AhS + k0w + 4);
            cpa16(sAl + SA_OFF(s,arA,acA),   AlS + k0w);
            cpa16(sAl + SA_OFF(s,arA,acA+4), AlS + k0w + 4);
            cpa16(sBh + SB_OFF(s,brA,bcA), WhS + (size_t)k0w*N);
            cpa16(sBl + SB_OFF(s,brA,bcA), WlS + (size_t)k0w*N);
            CP_COMMIT();
        }
        int cb = c%3;
        #pragma unroll
        for(int kk2 = 0; kk2 < 16; kk2 += 8){
            uint32_t ah[2][4], al[2][4];
            #pragma unroll
            for(int mt = 0; mt < 2; mt++){
                int m0 = wm*32 + mt*16;
                ah[mt][0] = sAh[SA_OFF(cb,m0+g  ,kk2+t  )]; al[mt][0] = sAl[SA_OFF(cb,m0+g  ,kk2+t  )];
                ah[mt][1] = sAh[SA_OFF(cb,m0+g+8,kk2+t  )]; al[mt][1] = sAl[SA_OFF(cb,m0+g+8,kk2+t  )];
                ah[mt][2] = sAh[SA_OFF(cb,m0+g  ,kk2+t+4)]; al[mt][2] = sAl[SA_OFF(cb,m0+g  ,kk2+t+4)];
                ah[mt][3] = sAh[SA_OFF(cb,m0+g+8,kk2+t+4)]; al[mt][3] = sAl[SA_OFF(cb,m0+g+8,kk2+t+4)];
            }
            #pragma unroll
            for(int nt = 0; nt < 8; nt++){
                int n0 = wn*64 + nt*8 + g;
                uint32_t bh0 = sBh[SB_OFF(cb,kk2+t  ,n0)], bl0 = sBl[SB_OFF(cb,kk2+t  ,n0)];
                uint32_t bh1 = sBh[SB_OFF(cb,kk2+t+4,n0)], bl1 = sBl[SB_OFF(cb,kk2+t+4,n0)];
                #pragma unroll
                for(int mt = 0; mt < 2; mt++){
                    MMA3(acc[mt][nt], ah[mt], al[mt], bh0, bh1, bl0, bl1);
                }
            }
        }
        __syncthreads();
    }
}

// generic GEMM: mode 0: f32 (+res*rscale); mode 1: split planes (opt gelu); mode 2: fused mix
__global__ void __launch_bounds__(512,1) k_gemm3(
        const uint32_t* __restrict__ Ah, const uint32_t* __restrict__ Al,
        const uint32_t* __restrict__ Wh, const uint32_t* __restrict__ Wl,
        const float* __restrict__ bbase, long bstr, int hop,
        const float* __restrict__ res, const float* __restrict__ rscale,
        const float* __restrict__ curin,
        float* __restrict__ C, uint32_t* __restrict__ Ch, uint32_t* __restrict__ Cl,
        int N, int K, int act, int mode){
    extern __shared__ uint32_t smem_u[];
    uint32_t* sAh = smem_u;
    uint32_t* sAl = sAh + 15360;
    uint32_t* sBh = sAl + 15360;
    uint32_t* sBl = sBh + 6528;
    int room = g_idx[hop];
    const float* bias = bbase + (size_t)room*bstr;
    int tid = threadIdx.x;
    int bm = blockIdx.y, bn = blockIdx.x;
    int warp = tid>>5, lane = tid&31;
    int g = lane>>2, t = lane&3;
    int wm = warp>>1, wn = warp&1;

    float acc[2][8][4] = {};
    gemm_core(Ah, Al, Wh, Wl, N, K, bm, bn, sAh, sAl, sBh, sBl, acc, tid, wm, wn, g, t);

    float gm = (mode == 2) ? g_gm : 0.f;
    #pragma unroll
    for(int mt = 0; mt < 2; mt++){
        int row = bm*256 + wm*32 + mt*16 + g;
        #pragma unroll
        for(int nt = 0; nt < 8; nt++){
            int col = bn*128 + wn*64 + nt*8 + 2*t;
            float2 bi = *(const float2*)&bias[col];
            float v0 = acc[mt][nt][0] + bi.x;
            float v1 = acc[mt][nt][1] + bi.y;
            float v2 = acc[mt][nt][2] + bi.x;
            float v3 = acc[mt][nt][3] + bi.y;
            if(act == 1){
                v0 = geluf(v0); v1 = geluf(v1); v2 = geluf(v2); v3 = geluf(v3);
            }
            size_t i0 = (size_t)row*N + col, i1 = (size_t)(row+8)*N + col;
            if(mode == 0){
                if(res){
                    float sc = rscale ? rscale[row>>10] : 1.0f;
                    float2 r0 = *(const float2*)&res[i0];
                    float2 r1 = *(const float2*)&res[i1];
                    v0 += r0.x*sc; v1 += r0.y*sc; v2 += r1.x*sc; v3 += r1.y*sc;
                }
                *(float2*)&C[i0] = make_float2(v0, v1);
                *(float2*)&C[i1] = make_float2(v2, v3);
            } else if(mode == 1){
                uint32_t hh, ll;
                size_t w0 = (size_t)row*(N>>1) + (col>>1);
                size_t w1 = (size_t)(row+8)*(N>>1) + (col>>1);
                split2(v0, v1, hh, ll); Ch[w0] = hh; Cl[w0] = ll;
                split2(v2, v3, hh, ll); Ch[w1] = hh; Cl[w1] = ll;
            } else {
                float2 r0 = *(const float2*)&res[i0];
                float2 r1 = *(const float2*)&res[i1];
                float2 c0 = *(const float2*)&curin[i0];
                float2 c1 = *(const float2*)&curin[i1];
                float x0 = r0.x + v0, x1 = r0.y + v1, x2 = r1.x + v2, x3 = r1.y + v3;
                *(float2*)&C[i0] = make_float2(c0.x + gm*(x0-c0.x), c0.y + gm*(x1-c0.y));
                *(float2*)&C[i1] = make_float2(c1.x + gm*(x2-c1.x), c1.y + gm*(x3-c1.y));
            }
        }
    }
}

// batched QKV: grid (8,16,3). z=0 -> q planes, z=1 -> k planes, z=2 -> v f32
__global__ void __launch_bounds__(512,1) k_qkv(
        const uint32_t* __restrict__ Ah, const uint32_t* __restrict__ Al,
        const uint32_t* __restrict__ Wp_h, const uint32_t* __restrict__ Wp_l,
        const float* __restrict__ bq, const float* __restrict__ bk_,
        const float* __restrict__ bv, int hop){
    extern __shared__ uint32_t smem_u[];
    uint32_t* sAh = smem_u;
    uint32_t* sAl = sAh + 15360;
    uint32_t* sBh = sAl + 15360;
    uint32_t* sBl = sBh + 6528;
    int room = g_idx[hop];
    int z = blockIdx.z;
    const float* bias = (z==0 ? bq : (z==1 ? bk_ : bv)) + (size_t)room*DD;
    const uint32_t* Wh = Wp_h + (size_t)z*SZP;
    const uint32_t* Wl = Wp_l + (size_t)z*SZP;
    int tid = threadIdx.x;
    int bm = blockIdx.y, bn = blockIdx.x;
    int warp = tid>>5, lane = tid&31;
    int g = lane>>2, t = lane&3;
    int wm = warp>>1, wn = warp&1;

    float acc[2][8][4] = {};
    gemm_core(Ah, Al, Wh, Wl, DD, DD, bm, bn, sAh, sAl, sBh, sBl, acc, tid, wm, wn, g, t);

    uint32_t* Ch = (z==0) ? g_qh : g_kh;
    uint32_t* Cl = (z==0) ? g_ql : g_kl;
    #pragma unroll
    for(int mt = 0; mt < 2; mt++){
        int row = bm*256 + wm*32 + mt*16 + g;
        #pragma unroll
        for(int nt = 0; nt < 8; nt++){
            int col = bn*128 + wn*64 + nt*8 + 2*t;
            float2 bi = *(const float2*)&bias[col];
            float v0 = acc[mt][nt][0] + bi.x;
            float v1 = acc[mt][nt][1] + bi.y;
            float v2 = acc[mt][nt][2] + bi.x;
            float v3 = acc[mt][nt][3] + bi.y;
            size_t i0 = (size_t)row*DD + col, i1 = (size_t)(row+8)*DD + col;
            if(z == 2){
                *(float2*)&g_v[i0] = make_float2(v0, v1);
                *(float2*)&g_v[i1] = make_float2(v2, v3);
            } else {
                uint32_t hh, ll;
                size_t w0 = (size_t)row*512 + (col>>1);
                size_t w1 = (size_t)(row+8)*512 + (col>>1);
                split2(v0, v1, hh, ll); Ch[w0] = hh; Cl[w0] = ll;
                split2(v2, v3, hh, ll); Ch[w1] = hh; Cl[w1] = ll;
            }
        }
    }
}

// ---------------- fused flash attention (bf16x3, online softmax) ----------------
__global__ void __launch_bounds__(128) k_flash(){
    int ti = 15 - (int)blockIdx.x;
    int bh = blockIdx.y; int b = bh>>4, h = bh&15;
    __shared__ uint32_t Qh[64][36], Ql[64][36];
    __shared__ uint32_t Kh[64][36], Kl[64][36];
    __shared__ uint32_t Vh[32][72], Vl[32][72];
    __shared__ float smax[2][64];
    __shared__ float sO[2][32][68];
    int tid = threadIdx.x;
    int warp = tid>>5, lane = tid&31;
    int g = lane>>2, t = lane&3;
    int wm = warp>>1, wn = warp&1;
    int vk2 = tid>>4, vn4 = tid&15;

    #pragma unroll
    for(int i = 0; i < 4; i++){
        int idx = tid + 128*i;
        int r = idx>>3, c = (idx&7)*4;
        size_t qoff = ((size_t)(b*TT + ti*64 + r))*512 + h*32 + c;
        *(uint4*)&Qh[r][c] = *(const uint4*)(g_qh + qoff);
        *(uint4*)&Ql[r][c] = *(const uint4*)(g_ql + qoff);
    }

    float mo[4], l[4], O[2][8][4];
    #pragma unroll
    for(int i = 0; i < 4; i++){ mo[i] = -1e30f; l[i] = 0.f; }
    #pragma unroll
    for(int a = 0; a < 2; a++)
        #pragma unroll
        for(int n2 = 0; n2 < 8; n2++)
            #pragma unroll
            for(int j = 0; j < 4; j++) O[a][n2][j] = 0.f;

    for(int kt = 0; kt <= ti; kt++){
        __syncthreads();
        #pragma unroll
        for(int i = 0; i < 4; i++){
            int idx = tid + 128*i;
            int r = idx>>3, c = (idx&7)*4;
            size_t koff = ((size_t)(b*TT + kt*64 + r))*512 + h*32 + c;
            *(uint4*)&Kh[r][c] = *(const uint4*)(g_kh + koff);
            *(uint4*)&Kl[r][c] = *(const uint4*)(g_kl + koff);
        }
        #pragma unroll
        for(int i = 0; i < 4; i++){
            int k2 = vk2 + 8*i;
            size_t voff = ((size_t)bh*512 + kt*32 + k2)*64 + vn4*4;
            *(uint4*)&Vh[k2][vn4*4] = *(const uint4*)(g_vh + voff);
            *(uint4*)&Vl[k2][vn4*4] = *(const uint4*)(g_vl + voff);
        }
        __syncthreads();

        float S[2][4][4];
        #pragma unroll
        for(int a = 0; a < 2; a++)
            #pragma unroll
            for(int n = 0; n < 4; n++)
                #pragma unroll
                for(int c = 0; c < 4; c++) S[a][n][c] = 0.f;
        #pragma unroll
        for(int kk2 = 0; kk2 < 32; kk2 += 8){
            uint32_t ah[2][4], al[2][4];
            #pragma unroll
            for(int mt = 0; mt < 2; mt++){
                int m0 = wm*32 + mt*16;
                ah[mt][0] = Qh[m0+g  ][kk2+t  ]; al[mt][0] = Ql[m0+g  ][kk2+t  ];
                ah[mt][1] = Qh[m0+g+8][kk2+t  ]; al[mt][1] = Ql[m0+g+8][kk2+t  ];
                ah[mt][2] = Qh[m0+g  ][kk2+t+4]; al[mt][2] = Ql[m0+g  ][kk2+t+4];
                ah[mt][3] = Qh[m0+g+8][kk2+t+4]; al[mt][3] = Ql[m0+g+8][kk2+t+4];
            }
            #pragma unroll
            for(int nt = 0; nt < 4; nt++){
                int n0 = wn*32 + nt*8 + g;
                uint32_t bh0 = Kh[n0][kk2+t  ], bl0 = Kl[n0][kk2+t  ];
                uint32_t bh1 = Kh[n0][kk2+t+4], bl1 = Kl[n0][kk2+t+4];
                #pragma unroll
                for(int mt = 0; mt < 2; mt++){
                    MMA3(S[mt][nt], ah[mt], al[mt], bh0, bh1, bl0, bl1);
                }
            }
        }
        float rmax[4] = {-1e30f,-1e30f,-1e30f,-1e30f};
        #pragma unroll
        for(int mt = 0; mt < 2; mt++)
        #pragma unroll
        for(int nt = 0; nt < 4; nt++)
        #pragma unroll
        for(int j = 0; j < 4; j++){
            float val = S[mt][nt][j]*0.125f;
            if(kt == ti){
                int row = wm*32 + mt*16 + g + ((j>>1)<<3);
                int col = wn*32 + nt*8 + 2*t + (j&1);
                if(col > row) val = -1e30f;
            }
            S[mt][nt][j] = val;
            int ri = mt*2 + (j>>1);
            rmax[ri] = fmaxf(rmax[ri], val);
        }
        #pragma unroll
        for(int i = 0; i < 4; i++){
            rmax[i] = fmaxf(rmax[i], __shfl_xor_sync(0xffffffffu, rmax[i], 1));
            rmax[i] = fmaxf(rmax[i], __shfl_xor_sync(0xffffffffu, rmax[i], 2));
        }
        if(t == 0){
            #pragma unroll
            for(int mt = 0; mt < 2; mt++){
                smax[wn][wm*32 + mt*16 + g    ] = rmax[mt*2];
                smax[wn][wm*32 + mt*16 + g + 8] = rmax[mt*2+1];
            }
        }
        __syncthreads();
        float mn[4], alp[4];
        #pragma unroll
        for(int mt = 0; mt < 2; mt++)
        #pragma unroll
        for(int rr = 0; rr < 2; rr++){
            int row = wm*32 + mt*16 + g + rr*8;
            float mm = fmaxf(smax[0][row], smax[1][row]);
            int i = mt*2 + rr;
            mn[i] = fmaxf(mo[i], mm);
            alp[i] = expf(mo[i] - mn[i]);
            mo[i] = mn[i];
        }
        float rs[4] = {0.f,0.f,0.f,0.f};
        #pragma unroll
        for(int mt = 0; mt < 2; mt++)
        #pragma unroll
        for(int nt = 0; nt < 4; nt++)
        #pragma unroll
        for(int j = 0; j < 4; j++){
            int i = mt*2 + (j>>1);
            float e = expf(S[mt][nt][j] - mn[i]);
            S[mt][nt][j] = e;
            rs[i] += e;
        }
        #pragma unroll
        for(int i = 0; i < 4; i++){
            rs[i] += __shfl_xor_sync(0xffffffffu, rs[i], 1);
            rs[i] += __shfl_xor_sync(0xffffffffu, rs[i], 2);
            l[i] = l[i]*alp[i] + rs[i];
        }
        #pragma unroll
        for(int mt = 0; mt < 2; mt++)
        #pragma unroll
        for(int n2 = 0; n2 < 8; n2++)
        #pragma unroll
        for(int j = 0; j < 4; j++)
            O[mt][n2][j] *= alp[mt*2 + (j>>1)];
        #pragma unroll
        for(int kg = 0; kg < 2; kg++){
            uint32_t ah[2][4], al[2][4];
            #pragma unroll
            for(int mt = 0; mt < 2; mt++){
                split2(S[mt][kg*2  ][0], S[mt][kg*2  ][1], ah[mt][0], al[mt][0]);
                split2(S[mt][kg*2  ][2], S[mt][kg*2  ][3], ah[mt][1], al[mt][1]);
                split2(S[mt][kg*2+1][0], S[mt][kg*2+1][1], ah[mt][2], al[mt][2]);
                split2(S[mt][kg*2+1][2], S[mt][kg*2+1][3], ah[mt][3], al[mt][3]);
            }
            int k2b = wn*16 + kg*8;
            #pragma unroll
            for(int n2 = 0; n2 < 8; n2++){
                int n0 = n2*8 + g;
                uint32_t bh0 = Vh[k2b+t  ][n0], bl0 = Vl[k2b+t  ][n0];
                uint32_t bh1 = Vh[k2b+t+4][n0], bl1 = Vl[k2b+t+4][n0];
                #pragma unroll
                for(int mt = 0; mt < 2; mt++){
                    MMA3(O[mt][n2], ah[mt], al[mt], bh0, bh1, bl0, bl1);
                }
            }
        }
    }
    __syncthreads();
    if(wn == 1){
        #pragma unroll
        for(int mt = 0; mt < 2; mt++)
        #pragma unroll
        for(int n2 = 0; n2 < 8; n2++)
        #pragma unroll
        for(int j = 0; j < 4; j++)
            sO[wm][lane][mt*32 + n2*4 + j] = O[mt][n2][j];
        #pragma unroll
        for(int i = 0; i < 4; i++) sO[wm][lane][64+i] = l[i];
    }
    __syncthreads();
    if(wn == 0){
        float inv[4];
        #pragma unroll
        for(int i = 0; i < 4; i++) inv[i] = 1.0f/(l[i] + sO[wm][lane][64+i]);
        #pragma unroll
        for(int mt = 0; mt < 2; mt++){
            int row0 = ti*64 + wm*32 + mt*16 + g;
            #pragma unroll
            for(int n2 = 0; n2 < 8; n2++){
                float o0 = (O[mt][n2][0] + sO[wm][lane][mt*32 + n2*4 + 0])*inv[mt*2];
                float o1 = (O[mt][n2][1] + sO[wm][lane][mt*32 + n2*4 + 1])*inv[mt*2];
                float o2 = (O[mt][n2][2] + sO[wm][lane][mt*32 + n2*4 + 2])*inv[mt*2+1];
                float o3 = (O[mt][n2][3] + sO[wm][lane][mt*32 + n2*4 + 3])*inv[mt*2+1];
                int col = n2*8 + 2*t;
                size_t w0 = ((size_t)(b*TT + row0))*512 + (h*64 + col)/2;
                size_t w1 = ((size_t)(b*TT + row0 + 8))*512 + (h*64 + col)/2;
                uint32_t hh, ll2;
                split2(o0, o1, hh, ll2); g_oh[w0] = hh; g_ol[w0] = ll2;
                split2(o2, o3, hh, ll2); g_oh[w1] = hh; g_ol[w1] = ll2;
            }
        }
    }
}

extern "C" void kernel_launch(void* const* d_in, const int* in_sizes, int n_in,
                              void* d_out, int out_size){
    const float* x         = (const float*)d_in[0];
    const float* summaries = (const float*)d_in[1];
    const float* ctx_w     = (const float*)d_in[2];
    const float* ctx_b     = (const float*)d_in[3];
    const float* base_adj  = (const float*)d_in[4];
    const float* warp_w    = (const float*)d_in[5];
    const float* warp_b    = (const float*)d_in[6];
    const float* gate_w    = (const float*)d_in[7];
    const float* gate_b    = (const float*)d_in[8];
    const float* g1_w      = (const float*)d_in[9];
    const float* g1_b      = (const float*)d_in[10];
    const float* g2_w      = (const float*)d_in[11];
    const float* g2_b      = (const float*)d_in[12];
    const float* ln1_g     = (const float*)d_in[13];
    const float* ln1_b     = (const float*)d_in[14];
    const float* wq        = (const float*)d_in[15];
    const float* bq        = (const float*)d_in[16];
    const float* wk        = (const float*)d_in[17];
    const float* bk        = (const float*)d_in[18];
    const float* wv        = (const float*)d_in[19];
    const float* bv        = (const float*)d_in[20];
    const float* wo        = (const float*)d_in[21];
    const float* bo        = (const float*)d_in[22];
    const float* ln2_g     = (const float*)d_in[23];
    const float* ln2_b     = (const float*)d_in[24];
    const float* ff1_w     = (const float*)d_in[25];
    const float* ff1_b     = (const float*)d_in[26];
    const float* ff2_w     = (const float*)d_in[27];
    const float* ff2_b     = (const float*)d_in[28];
    float* out = (float*)d_out;

    float *p_cur, *p_xo, *p_v, *p_gate;
    uint32_t *p_oh,*p_ol,*p_nh,*p_nl,*p_mh,*p_ml,*p_wph,*p_wpl;
    cudaGetSymbolAddress((void**)&p_cur,  g_cur);
    cudaGetSymbolAddress((void**)&p_xo,   g_xo);
    cudaGetSymbolAddress((void**)&p_v,    g_v);
    cudaGetSymbolAddress((void**)&p_gate, g_gate);
    cudaGetSymbolAddress((void**)&p_oh, g_oh);  cudaGetSymbolAddress((void**)&p_ol, g_ol);
    cudaGetSymbolAddress((void**)&p_nh, g_normh); cudaGetSymbolAddress((void**)&p_nl, g_norml);
    cudaGetSymbolAddress((void**)&p_mh, g_midh); cudaGetSymbolAddress((void**)&p_ml, g_midl);
    cudaGetSymbolAddress((void**)&p_wph, g_wph); cudaGetSymbolAddress((void**)&p_wpl, g_wpl);

    cudaFuncSetAttribute(k_gemm3, cudaFuncAttributeMaxDynamicSharedMemorySize, DSMEM_BYTES);
    cudaFuncSetAttribute(k_qkv,   cudaFuncAttributeMaxDynamicSharedMemorySize, DSMEM_BYTES);

    // ---- router ----
    k_meanT_part<<<dim3(BB,32),256>>>(x);
    k_meanT_reduce<<<BB,256>>>();
    k_ctx<<<dim3(BB,32),128>>>(ctx_w, ctx_b);
    k_route1<<<dim3(BB,80),128>>>(warp_w, summaries, gate_w);
    k_route2<<<1,32>>>(base_adj, warp_b, gate_b,
                       out + BTD, out + BTD + 32, out + BTD + 32 + 256);

    // ---- 3 hops ----
    for(int hop = 0; hop < 3; hop++){
        const float* cin = (hop == 0) ? x : p_cur;
        float* cout = (hop == 2) ? out : p_cur;

        k_packw4<<<dim3(SZP/256,1,4),256>>>(wq, wk, wv, wo, p_wph, p_wpl, hop);
        k_packw<<<SZF/256,256>>>(ff1_w, p_wph+4*SZP,     p_wpl+4*SZP,     DFF, hop, (long)DD*DFF);
        k_packw<<<SZF/256,256>>>(ff2_w, p_wph+4*SZP+SZF, p_wpl+4*SZP+SZF, DD,  hop, (long)DFF*DD);

        if(hop > 0){
            k_meanT_part<<<dim3(BB,32),256>>>(cin);
            k_meanT_reduce<<<BB,256>>>();
        }
        k_g1<<<dim3(BB,16),256>>>(g1_w, g1_b, hop);
        k_g2<<<1,256>>>(g2_w, g2_b, hop);
        k_ln2<<<BT,256>>>(cin, ln1_g, ln1_b, hop, p_gate, p_nh, p_nl);
        k_qkv<<<dim3(8,16,3),512,DSMEM_BYTES>>>(p_nh, p_nl, p_wph, p_wpl, bq, bk, bv, hop);
        k_vsplit<<<BT/2,256>>>(p_v);
        k_flash<<<dim3(16,BB*HH),128>>>();
        k_gemm3<<<dim3(8,16),512,DSMEM_BYTES>>>(p_oh,p_ol, p_wph+3*SZP,p_wpl+3*SZP, bo, DD, hop,
                                    cin, p_gate, nullptr, p_xo, nullptr,nullptr, DD, DD, 0, 0);
        k_ln2<<<BT,256>>>(p_xo, ln2_g, ln2_b, hop, nullptr, p_nh, p_nl);
        k_gemm3<<<dim3(32,16),512,DSMEM_BYTES>>>(p_nh,p_nl, p_wph+4*SZP,p_wpl+4*SZP, ff1_b, DFF, hop,
                                    nullptr,nullptr,nullptr, nullptr, p_mh,p_ml, DFF, DD, 1, 1);
        k_gemm3<<<dim3(8,16),512,DSMEM_BYTES>>>(p_mh,p_ml, p_wph+4*SZP+SZF,p_wpl+4*SZP+SZF, ff2_b, DD, hop,
                                    p_xo, nullptr, cin, cout, nullptr,nullptr, DD, DFF, 0, 2);
    }
}

// round 14
// speedup vs baseline: 1.1596x; 1.1596x over previous
#include <cuda_runtime.h>
#include <cuda_bf16.h>
#include <math.h>
#include <stdint.h>

#define BB 4
#define TT 1024
#define DD 1024
#define HH 16
#define DFF 4096
#define RR 8
#define BT (BB*TT)
#define BTD (BB*TT*DD)
#define SZP (512*1024)
#define SZF 2097152

// ---------------- device scratch ----------------
__device__ float g_cur[BTD];
__device__ float g_xo[BTD];
__device__ uint32_t g_qh[BT*512], g_ql[BT*512];
__device__ uint32_t g_kh[BT*512], g_kl[BT*512];
__device__ uint32_t g_vh[BB*HH*512*64], g_vl[BB*HH*512*64];
__device__ uint32_t g_oh[BT*512], g_ol[BT*512];
__device__ uint32_t g_normh[BT*512], g_norml[BT*512];
__device__ uint32_t g_midh[BT*2048], g_midl[BT*2048];
__device__ uint32_t g_wph[4*SZP + 2*SZF], g_wpl[4*SZP + 2*SZF];
__device__ float g_part[BB*32*DD];
__device__ float g_ctxm[BB*DD];
__device__ float g_ctx[BB*DD];
__device__ float g_rt[BB*80];
__device__ float g_h1[BB*256];
__device__ float g_gate[BB];
__device__ float g_gm;
__device__ int   g_idx[3];

__device__ __forceinline__ float geluf(float x){
    return 0.5f*x*(1.0f+erff(x*0.7071067811865476f));
}
__device__ __forceinline__ void split2(float x, float y, uint32_t &hi, uint32_t &lo){
    __nv_bfloat16 xh = __float2bfloat16_rn(x);
    __nv_bfloat16 yh = __float2bfloat16_rn(y);
    __nv_bfloat162 h; h.x = xh; h.y = yh;
    __nv_bfloat162 l; l.x = __float2bfloat16_rn(x - __bfloat162float(xh));
    l.y = __float2bfloat16_rn(y - __bfloat162float(yh));
    hi = *(uint32_t*)&h; lo = *(uint32_t*)&l;
}
__device__ __forceinline__ void mma_bf16(float* c, uint32_t a0, uint32_t a1, uint32_t a2, uint32_t a3,
                                         uint32_t b0, uint32_t b1){
    asm volatile("mma.sync.aligned.m16n8k16.row.col.f32.bf16.bf16.f32 "
        "{%0,%1,%2,%3},{%4,%5,%6,%7},{%8,%9},{%0,%1,%2,%3};"
        : "+f"(c[0]), "+f"(c[1]), "+f"(c[2]), "+f"(c[3])
        : "r"(a0), "r"(a1), "r"(a2), "r"(a3), "r"(b0), "r"(b1));
}
#define MMA3(accp, AH, AL, BH0, BH1, BL0, BL1) \
    mma_bf16(accp, AH[0],AH[1],AH[2],AH[3], BH0, BH1); \
    mma_bf16(accp, AH[0],AH[1],AH[2],AH[3], BL0, BL1); \
    mma_bf16(accp, AL[0],AL[1],AL[2],AL[3], BH0, BH1);

__device__ __forceinline__ void cpa16(void* dst, const void* src){
    uint32_t d = (uint32_t)__cvta_generic_to_shared(dst);
    asm volatile("cp.async.cg.shared.global [%0], [%1], 16;" :: "r"(d), "l"(src));
}
#define CP_COMMIT() asm volatile("cp.async.commit_group;")

// ---------------- small kernels ----------------
__global__ void k_meanT_part(const float* __restrict__ in){
    int b = blockIdx.x, c = blockIdx.y;
    int t0 = c*32;
    for(int d = threadIdx.x; d < DD; d += 256){
        float s = 0.f;
        for(int t = t0; t < t0+32; t++) s += in[((size_t)(b*TT+t))*DD + d];
        g_part[(size_t)(b*32+c)*DD + d] = s;
    }
}
__global__ void k_meanT_reduce(){
    int b = blockIdx.x;
    for(int d = threadIdx.x; d < DD; d += 256){
        float s = 0.f;
        for(int c = 0; c < 32; c++) s += g_part[(size_t)(b*32+c)*DD + d];
        g_ctxm[b*DD + d] = s*(1.0f/TT);
    }
}
__global__ void k_ctx(const float* __restrict__ W, const float* __restrict__ bias){
    int b = blockIdx.x; int n0 = blockIdx.y*32;
    int lane = threadIdx.x & 31, q = threadIdx.x >> 5;
    const float* xv = &g_ctxm[b*DD];
    float s = 0.f;
    int k0 = q*256;
    for(int k = k0; k < k0+256; k++) s += xv[k]*W[(size_t)k*DD + n0 + lane];
    __shared__ float red[4][32];
    red[q][lane] = s; __syncthreads();
    if(q == 0)
        g_ctx[b*DD + n0 + lane] = red[0][lane]+red[1][lane]+red[2][lane]+red[3][lane] + bias[n0+lane];
}
__global__ void __launch_bounds__(128) k_route1(const float* __restrict__ warp_w,
        const float* __restrict__ summaries, const float* __restrict__ gate_w){
    int b = blockIdx.x, o = blockIdx.y;
    int tid = threadIdx.x;
    const float* xv = &g_ctx[b*DD];
    float s = 0.f;
    if(o < 64){
        for(int k = tid; k < DD; k += 128) s += xv[k]*warp_w[(size_t)k*64 + o];
    } else if(o < 72){
        const float* sr = summaries + (size_t)(o-64)*DD;
        for(int k = tid; k < DD; k += 128) s += xv[k]*sr[k];
    } else {
        for(int k = tid; k < DD; k += 128) s += xv[k]*gate_w[k*RR + (o-72)];
    }
    __shared__ float red[128];
    red[tid] = s; __syncthreads();
    for(int off = 64; off >= 1; off >>= 1){
        if(tid < off) red[tid] += red[tid+off];
        __syncthreads();
    }
    if(tid == 0) g_rt[b*80 + o] = red[0];
}
__global__ void k_route2(const float* __restrict__ base_adj,
                         const float* __restrict__ warp_b, const float* __restrict__ gate_b,
                         float* __restrict__ out_gs, float* __restrict__ out_adj,
                         float* __restrict__ out_mh){
    __shared__ float s_gs[BB][RR];
    int tid = threadIdx.x;
    if(tid < 32){
        int b = tid/8, i = tid%8;
        float v[8]; float mx = -1e30f;
        for(int j = 0; j < 8; j++){
            v[j] = base_adj[i*8+j] + (g_rt[b*80 + i*8 + j] + warp_b[i*8+j])*0.1f;
            mx = fmaxf(mx, v[j]);
        }
        float sum = 0.f;
        for(int j = 0; j < 8; j++){ v[j] = expf(v[j]-mx); sum += v[j]; }
        float inv = 1.0f/sum;
        float boost = 0.f;
        for(int j = 0; j < 8; j++){
            float a = v[j]*inv;
            out_adj[(b*8+i)*8 + j] = a;
            boost += a*g_rt[b*80 + 64 + j];
        }
        float gl = g_rt[b*80 + 72 + i] + gate_b[i];
        float gs = 1.0f/(1.0f+expf(-(gl+boost)*0.5f));
        out_gs[b*8+i] = gs;
        s_gs[b][i] = gs;
    }
    __syncthreads();
    if(tid == 0){
        float m[RR];
        for(int r = 0; r < 8; r++) m[r] = 0.25f*(s_gs[0][r]+s_gs[1][r]+s_gs[2][r]+s_gs[3][r]);
        for(int h = 0; h < 3; h++){
            int best = 0; float bv = -1e30f;
            for(int r = 0; r < 8; r++) if(m[r] > bv){ bv = m[r]; best = r; }
            g_idx[h] = best; m[best] = -1e30f;
        }
        out_mh[0] = 3.0f;
    }
}
__global__ void __launch_bounds__(256) k_g1(const float* __restrict__ g1_w, const float* __restrict__ g1_b, int hop){
    int room = g_idx[hop];
    int b = blockIdx.x;
    int tid = threadIdx.x;
    int n = blockIdx.y*16 + (tid & 15);
    int slice = tid >> 4;
    const float* W = g1_w + (size_t)room*DD*256;
    const float* xv = &g_ctxm[b*DD];
    float s = 0.f;
    int k0 = slice*64;
    for(int k = k0; k < k0+64; k++) s += xv[k]*W[(size_t)k*256 + n];
    __shared__ float red[256];
    red[tid] = s; __syncthreads();
    if(tid < 16){
        float tot = 0.f;
        for(int sl = 0; sl < 16; sl++) tot += red[tid + 16*sl];
        int nn = blockIdx.y*16 + tid;
        g_h1[b*256 + nn] = geluf(tot + g1_b[room*256 + nn]);
    }
}
__global__ void k_g2(const float* __restrict__ g2_w, const float* __restrict__ g2_b, int hop){
    int room = g_idx[hop];
    __shared__ float red[256];
    int tid = threadIdx.x;
    int b = tid/64, lane = tid%64;
    const float* W = g2_w + room*256;
    float s = 0.f;
    for(int k = lane; k < 256; k += 64) s += g_h1[b*256 + k]*W[k];
    red[tid] = s; __syncthreads();
    for(int off = 32; off >= 1; off >>= 1){
        if(lane < off) red[tid] += red[tid+off];
        __syncthreads();
    }
    if(lane == 0){
        float gate = 1.0f/(1.0f+expf(-(red[tid]+g2_b[room])));
        g_gate[b] = gate;
    }
    __syncthreads();
    if(tid == 0) g_gm = 0.25f*(g_gate[0]+g_gate[1]+g_gate[2]+g_gate[3]);
}

// weight pre-pack (single weight): vertical k-pairs, layout [K/2][N]
__global__ void k_packw(const float* __restrict__ Wb, uint32_t* __restrict__ oh, uint32_t* __restrict__ ol,
                        int N, int hop, long wstr){
    int room = g_idx[hop];
    const float* W = Wb + (size_t)room*wstr;
    int i = blockIdx.x*256 + threadIdx.x;
    int k2 = i / N, n = i % N;
    float a = W[(size_t)(2*k2)*N + n];
    float b = W[(size_t)(2*k2+1)*N + n];
    uint32_t hh, ll; split2(a, b, hh, ll);
    oh[i] = hh; ol[i] = ll;
}
// merged pack for the 4 DxD weights: z selects weight
__global__ void k_packw4(const float* __restrict__ w0, const float* __restrict__ w1,
                         const float* __restrict__ w2, const float* __restrict__ w3,
                         uint32_t* __restrict__ oh, uint32_t* __restrict__ ol, int hop){
    int room = g_idx[hop];
    int z = blockIdx.z;
    const float* Wb = (z==0) ? w0 : (z==1) ? w1 : (z==2) ? w2 : w3;
    const float* W = Wb + (size_t)room*DD*DD;
    int i = blockIdx.x*256 + threadIdx.x;
    int k2 = i / DD, n = i % DD;
    float a = W[(size_t)(2*k2)*DD + n];
    float b = W[(size_t)(2*k2+1)*DD + n];
    uint32_t hh, ll; split2(a, b, hh, ll);
    oh[(size_t)z*SZP + i] = hh; ol[(size_t)z*SZP + i] = ll;
}

// layernorm -> split bf16 planes
__global__ void __launch_bounds__(256) k_ln2(const float* __restrict__ in,
                     const float* __restrict__ gb, const float* __restrict__ bb,
                     int hop, const float* __restrict__ gate,
                     uint32_t* __restrict__ oh, uint32_t* __restrict__ ol){
    int row = blockIdx.x; int b = row >> 10;
    int room = g_idx[hop];
    float sc = gate ? gate[b] : 1.0f;
    float4 v = ((const float4*)(in + (size_t)row*DD))[threadIdx.x];
    v.x *= sc; v.y *= sc; v.z *= sc; v.w *= sc;
    __shared__ float rs[256], rq[256];
    rs[threadIdx.x] = v.x+v.y+v.z+v.w;
    rq[threadIdx.x] = v.x*v.x+v.y*v.y+v.z*v.z+v.w*v.w;
    __syncthreads();
    for(int off = 128; off >= 1; off >>= 1){
        if(threadIdx.x < off){ rs[threadIdx.x] += rs[threadIdx.x+off]; rq[threadIdx.x] += rq[threadIdx.x+off]; }
        __syncthreads();
    }
    float mean = rs[0]*(1.0f/DD);
    float var  = rq[0]*(1.0f/DD) - mean*mean;
    float inv  = rsqrtf(var + 1e-5f);
    float4 g4 = ((const float4*)(gb + (size_t)room*DD))[threadIdx.x];
    float4 b4 = ((const float4*)(bb + (size_t)room*DD))[threadIdx.x];
    float o0 = (v.x-mean)*inv*g4.x + b4.x;
    float o1 = (v.y-mean)*inv*g4.y + b4.y;
    float o2 = (v.z-mean)*inv*g4.z + b4.z;
    float o3 = (v.w-mean)*inv*g4.w + b4.w;
    uint32_t h0,l0,h1,l1;
    split2(o0,o1,h0,l0); split2(o2,o3,h1,l1);
    size_t w = (size_t)row*512 + threadIdx.x*2;
    *(uint2*)&oh[w] = make_uint2(h0,h1);
    *(uint2*)&ol[w] = make_uint2(l0,l1);
}

// ---------------- GEMM core: BK=32, 3-stage cp.async ring (R9/R12 layout) ----------------
#define SA_OFF(s,r,c) ((s)*2560 + (r)*20 + (c))
#define SB_OFF(s,k,c) ((s)*2176 + (k)*136 + (c))
#define DSMEM_BYTES ((7680*2 + 6528*2)*4)

__device__ __forceinline__ void gemm_core(
        const uint32_t* __restrict__ Ah, const uint32_t* __restrict__ Al,
        const uint32_t* __restrict__ Wh, const uint32_t* __restrict__ Wl,
        int N, int K, int bm, int bn,
        uint32_t* sAh, uint32_t* sAl, uint32_t* sBh, uint32_t* sBl,
        float acc[2][8][4], int tid, int wm, int wn, int g, int t){
    int halfK = K >> 1;
    int nC = K >> 5;
    int arA = tid>>2, acA = (tid&3)*4;
    int brA = tid>>5, bcA = (tid&31)*4;
    const uint32_t* AhS = Ah + (size_t)(bm*128 + arA)*halfK + acA;
    const uint32_t* AlS = Al + (size_t)(bm*128 + arA)*halfK + acA;
    const uint32_t* WhS = Wh + (size_t)brA*N + bn*128 + bcA;
    const uint32_t* WlS = Wl + (size_t)brA*N + bn*128 + bcA;
    const size_t a64 = (size_t)64*halfK;
    const size_t b8  = (size_t)8*N;

    #pragma unroll
    for(int s = 0; s < 2; s++){
        if(s < nC){
            int k0w = s*16;
            cpa16(sAh + SA_OFF(s,arA,acA), AhS + k0w);
            cpa16(sAh + SA_OFF(s,arA+64,acA), AhS + a64 + k0w);
            cpa16(sAl + SA_OFF(s,arA,acA), AlS + k0w);
            cpa16(sAl + SA_OFF(s,arA+64,acA), AlS + a64 + k0w);
            cpa16(sBh + SB_OFF(s,brA,bcA), WhS + (size_t)k0w*N);
            cpa16(sBh + SB_OFF(s,brA+8,bcA), WhS + (size_t)k0w*N + b8);
            cpa16(sBl + SB_OFF(s,brA,bcA), WlS + (size_t)k0w*N);
            cpa16(sBl + SB_OFF(s,brA+8,bcA), WlS + (size_t)k0w*N + b8);
            CP_COMMIT();
        }
    }
    for(int c = 0; c < nC; c++){
        if(c+1 < nC) asm volatile("cp.async.wait_group 1;");
        else         asm volatile("cp.async.wait_group 0;");
        __syncthreads();
        if(c+2 < nC){
            int s = (c+2)%3;
            int k0w = (c+2)*16;
            cpa16(sAh + SA_OFF(s,arA,acA), AhS + k0w);
            cpa16(sAh + SA_OFF(s,arA+64,acA), AhS + a64 + k0w);
            cpa16(sAl + SA_OFF(s,arA,acA), AlS + k0w);
            cpa16(sAl + SA_OFF(s,arA+64,acA), AlS + a64 + k0w);
            cpa16(sBh + SB_OFF(s,brA,bcA), WhS + (size_t)k0w*N);
            cpa16(sBh + SB_OFF(s,brA+8,bcA), WhS + (size_t)k0w*N + b8);
            cpa16(sBl + SB_OFF(s,brA,bcA), WlS + (size_t)k0w*N);
            cpa16(sBl + SB_OFF(s,brA+8,bcA), WlS + (size_t)k0w*N + b8);
            CP_COMMIT();
        }
        int cb = c%3;
        #pragma unroll
        for(int kk2 = 0; kk2 < 16; kk2 += 8){
            uint32_t ah[2][4], al[2][4];
            #pragma unroll
            for(int mt = 0; mt < 2; mt++){
                int m0 = wm*32 + mt*16;
                ah[mt][0] = sAh[SA_OFF(cb,m0+g  ,kk2+t  )]; al[mt][0] = sAl[SA_OFF(cb,m0+g  ,kk2+t  )];
                ah[mt][1] = sAh[SA_OFF(cb,m0+g+8,kk2+t  )]; al[mt][1] = sAl[SA_OFF(cb,m0+g+8,kk2+t  )];
                ah[mt][2] = sAh[SA_OFF(cb,m0+g  ,kk2+t+4)]; al[mt][2] = sAl[SA_OFF(cb,m0+g  ,kk2+t+4)];
                ah[mt][3] = sAh[SA_OFF(cb,m0+g+8,kk2+t+4)]; al[mt][3] = sAl[SA_OFF(cb,m0+g+8,kk2+t+4)];
            }
            #pragma unroll
            for(int nt = 0; nt < 8; nt++){
                int n0 = wn*64 + nt*8 + g;
                uint32_t bh0 = sBh[SB_OFF(cb,kk2+t  ,n0)], bl0 = sBl[SB_OFF(cb,kk2+t  ,n0)];
                uint32_t bh1 = sBh[SB_OFF(cb,kk2+t+4,n0)], bl1 = sBl[SB_OFF(cb,kk2+t+4,n0)];
                #pragma unroll
                for(int mt = 0; mt < 2; mt++){
                    MMA3(acc[mt][nt], ah[mt], al[mt], bh0, bh1, bl0, bl1);
                }
            }
        }
        __syncthreads();
    }
}

// generic GEMM: mode 0: f32 (+res*rscale); mode 1: split planes (opt gelu); mode 2: fused mix
__global__ void __launch_bounds__(256,2) k_gemm3(
        const uint32_t* __restrict__ Ah, const uint32_t* __restrict__ Al,
        const uint32_t* __restrict__ Wh, const uint32_t* __restrict__ Wl,
        const float* __restrict__ bbase, long bstr, int hop,
        const float* __restrict__ res, const float* __restrict__ rscale,
        const float* __restrict__ curin,
        float* __restrict__ C, uint32_t* __restrict__ Ch, uint32_t* __restrict__ Cl,
        int N, int K, int act, int mode){
    extern __shared__ uint32_t smem_u[];
    uint32_t* sAh = smem_u;
    uint32_t* sAl = sAh + 7680;
    uint32_t* sBh = sAl + 7680;
    uint32_t* sBl = sBh + 6528;
    int room = g_idx[hop];
    const float* bias = bbase + (size_t)room*bstr;
    int tid = threadIdx.x;
    int bm = blockIdx.y, bn = blockIdx.x;
    int warp = tid>>5, lane = tid&31;
    int g = lane>>2, t = lane&3;
    int wm = warp>>1, wn = warp&1;

    float acc[2][8][4] = {};
    gemm_core(Ah, Al, Wh, Wl, N, K, bm, bn, sAh, sAl, sBh, sBl, acc, tid, wm, wn, g, t);

    float gm = (mode == 2) ? g_gm : 0.f;
    #pragma unroll
    for(int mt = 0; mt < 2; mt++){
        int row = bm*128 + wm*32 + mt*16 + g;
        #pragma unroll
        for(int nt = 0; nt < 8; nt++){
            int col = bn*128 + wn*64 + nt*8 + 2*t;
            float2 bi = *(const float2*)&bias[col];
            float v0 = acc[mt][nt][0] + bi.x;
            float v1 = acc[mt][nt][1] + bi.y;
            float v2 = acc[mt][nt][2] + bi.x;
            float v3 = acc[mt][nt][3] + bi.y;
            if(act == 1){
                v0 = geluf(v0); v1 = geluf(v1); v2 = geluf(v2); v3 = geluf(v3);
            }
            size_t i0 = (size_t)row*N + col, i1 = (size_t)(row+8)*N + col;
            if(mode == 0){
                if(res){
                    float sc = rscale ? rscale[row>>10] : 1.0f;
                    float2 r0 = *(const float2*)&res[i0];
                    float2 r1 = *(const float2*)&res[i1];
                    v0 += r0.x*sc; v1 += r0.y*sc; v2 += r1.x*sc; v3 += r1.y*sc;
                }
                *(float2*)&C[i0] = make_float2(v0, v1);
                *(float2*)&C[i1] = make_float2(v2, v3);
            } else if(mode == 1){
                uint32_t hh, ll;
                size_t w0 = (size_t)row*(N>>1) + (col>>1);
                size_t w1 = (size_t)(row+8)*(N>>1) + (col>>1);
                split2(v0, v1, hh, ll); Ch[w0] = hh; Cl[w0] = ll;
                split2(v2, v3, hh, ll); Ch[w1] = hh; Cl[w1] = ll;
            } else {
                float2 r0 = *(const float2*)&res[i0];
                float2 r1 = *(const float2*)&res[i1];
                float2 c0 = *(const float2*)&curin[i0];
                float2 c1 = *(const float2*)&curin[i1];
                float x0 = r0.x + v0, x1 = r0.y + v1, x2 = r1.x + v2, x3 = r1.y + v3;
                *(float2*)&C[i0] = make_float2(c0.x + gm*(x0-c0.x), c0.y + gm*(x1-c0.y));
                *(float2*)&C[i1] = make_float2(c1.x + gm*(x2-c1.x), c1.y + gm*(x3-c1.y));
            }
        }
    }
}

// batched QKV: grid (8,32,3). z=0 -> q planes, z=1 -> k planes, z=2 -> V planes (fused vsplit)
__global__ void __launch_bounds__(256,2) k_qkv(
        const uint32_t* __restrict__ Ah, const uint32_t* __restrict__ Al,
        const uint32_t* __restrict__ Wp_h, const uint32_t* __restrict__ Wp_l,
        const float* __restrict__ bq, const float* __restrict__ bk_,
        const float* __restrict__ bv, int hop){
    extern __shared__ uint32_t smem_u[];
    uint32_t* sAh = smem_u;
    uint32_t* sAl = sAh + 7680;
    uint32_t* sBh = sAl + 7680;
    uint32_t* sBl = sBh + 6528;
    int room = g_idx[hop];
    int z = blockIdx.z;
    const float* bias = (z==0 ? bq : (z==1 ? bk_ : bv)) + (size_t)room*DD;
    const uint32_t* Wh = Wp_h + (size_t)z*SZP;
    const uint32_t* Wl = Wp_l + (size_t)z*SZP;
    int tid = threadIdx.x;
    int bm = blockIdx.y, bn = blockIdx.x;
    int warp = tid>>5, lane = tid&31;
    int g = lane>>2, t = lane&3;
    int wm = warp>>1, wn = warp&1;

    float acc[2][8][4] = {};
    gemm_core(Ah, Al, Wh, Wl, DD, DD, bm, bn, sAh, sAl, sBh, sBl, acc, tid, wm, wn, g, t);

    uint32_t* Ch = (z==0) ? g_qh : g_kh;
    uint32_t* Cl = (z==0) ? g_ql : g_kl;
    #pragma unroll
    for(int mt = 0; mt < 2; mt++){
        int row = bm*128 + wm*32 + mt*16 + g;
        #pragma unroll
        for(int nt = 0; nt < 8; nt++){
            int col = bn*128 + wn*64 + nt*8 + 2*t;
            float2 bi = *(const float2*)&bias[col];
            float v0 = acc[mt][nt][0] + bi.x;
            float v1 = acc[mt][nt][1] + bi.y;
            float v2 = acc[mt][nt][2] + bi.x;
            float v3 = acc[mt][nt][3] + bi.y;
            if(z == 2){
                // fused V split: pair adjacent rows via lane^4 exchange (g even <-> g odd)
                float p0 = __shfl_xor_sync(0xffffffffu, v0, 4);
                float p1 = __shfl_xor_sync(0xffffffffu, v1, 4);
                float p2 = __shfl_xor_sync(0xffffffffu, v2, 4);
                float p3 = __shfl_xor_sync(0xffffffffu, v3, 4);
                if((g & 1) == 0){
                    int b = row >> 10;
                    int h = col >> 6, dh = col & 63;
                    int k2a = (row & (TT-1)) >> 1;
                    int k2b = ((row + 8) & (TT-1)) >> 1;
                    uint32_t h0,l0,h1,l1;
                    size_t oa = ((size_t)(b*HH + h)*512 + k2a)*64 + dh;
                    size_t ob = ((size_t)(b*HH + h)*512 + k2b)*64 + dh;
                    split2(v0, p0, h0, l0); split2(v1, p1, h1, l1);
                    *(uint2*)(g_vh + oa) = make_uint2(h0, h1);
                    *(uint2*)(g_vl + oa) = make_uint2(l0, l1);
                    split2(v2, p2, h0, l0); split2(v3, p3, h1, l1);
                    *(uint2*)(g_vh + ob) = make_uint2(h0, h1);
                    *(uint2*)(g_vl + ob) = make_uint2(l0, l1);
                }
            } else {
                uint32_t hh, ll;
                size_t w0 = (size_t)row*512 + (col>>1);
                size_t w1 = (size_t)(row+8)*512 + (col>>1);
                split2(v0, v1, hh, ll); Ch[w0] = hh; Cl[w0] = ll;
                split2(v2, v3, hh, ll); Ch[w1] = hh; Cl[w1] = ll;
            }
        }
    }
}

// ---------------- fused flash attention (bf16x3, online softmax) ----------------
__global__ void __launch_bounds__(128) k_flash(){
    int ti = 15 - (int)blockIdx.x;
    int bh = blockIdx.y; int b = bh>>4, h = bh&15;
    __shared__ uint32_t Qh[64][36], Ql[64][36];
    __shared__ uint32_t Kh[64][36], Kl[64][36];
    __shared__ uint32_t Vh[32][72], Vl[32][72];
    __shared__ float smax[2][64];
    __shared__ float sO[2][32][68];
    int tid = threadIdx.x;
    int warp = tid>>5, lane = tid&31;
    int g = lane>>2, t = lane&3;
    int wm = warp>>1, wn = warp&1;
    int vk2 = tid>>4, vn4 = tid&15;

    #pragma unroll
    for(int i = 0; i < 4; i++){
        int idx = tid + 128*i;
        int r = idx>>3, c = (idx&7)*4;
        size_t qoff = ((size_t)(b*TT + ti*64 + r))*512 + h*32 + c;
        *(uint4*)&Qh[r][c] = *(const uint4*)(g_qh + qoff);
        *(uint4*)&Ql[r][c] = *(const uint4*)(g_ql + qoff);
    }

    float mo[4], l[4], O[2][8][4];
    #pragma unroll
    for(int i = 0; i < 4; i++){ mo[i] = -1e30f; l[i] = 0.f; }
    #pragma unroll
    for(int a = 0; a < 2; a++)
        #pragma unroll
        for(int n2 = 0; n2 < 8; n2++)
            #pragma unroll
            for(int j = 0; j < 4; j++) O[a][n2][j] = 0.f;

    for(int kt = 0; kt <= ti; kt++){
        __syncthreads();
        #pragma unroll
        for(int i = 0; i < 4; i++){
            int idx = tid + 128*i;
            int r = idx>>3, c = (idx&7)*4;
            size_t koff = ((size_t)(b*TT + kt*64 + r))*512 + h*32 + c;
            *(uint4*)&Kh[r][c] = *(const uint4*)(g_kh + koff);
            *(uint4*)&Kl[r][c] = *(const uint4*)(g_kl + koff);
        }
        #pragma unroll
        for(int i = 0; i < 4; i++){
            int k2 = vk2 + 8*i;
            size_t voff = ((size_t)bh*512 + kt*32 + k2)*64 + vn4*4;
            *(uint4*)&Vh[k2][vn4*4] = *(const uint4*)(g_vh + voff);
            *(uint4*)&Vl[k2][vn4*4] = *(const uint4*)(g_vl + voff);
        }
        __syncthreads();

        float S[2][4][4];
        #pragma unroll
        for(int a = 0; a < 2; a++)
            #pragma unroll
            for(int n = 0; n < 4; n++)
                #pragma unroll
                for(int c = 0; c < 4; c++) S[a][n][c] = 0.f;
        #pragma unroll
        for(int kk2 = 0; kk2 < 32; kk2 += 8){
            uint32_t ah[2][4], al[2][4];
            #pragma unroll
            for(int mt = 0; mt < 2; mt++){
                int m0 = wm*32 + mt*16;
                ah[mt][0] = Qh[m0+g  ][kk2+t  ]; al[mt][0] = Ql[m0+g  ][kk2+t  ];
                ah[mt][1] = Qh[m0+g+8][kk2+t  ]; al[mt][1] = Ql[m0+g+8][kk2+t  ];
                ah[mt][2] = Qh[m0+g  ][kk2+t+4]; al[mt][2] = Ql[m0+g  ][kk2+t+4];
                ah[mt][3] = Qh[m0+g+8][kk2+t+4]; al[mt][3] = Ql[m0+g+8][kk2+t+4];
            }
            #pragma unroll
            for(int nt = 0; nt < 4; nt++){
                int n0 = wn*32 + nt*8 + g;
                uint32_t bh0 = Kh[n0][kk2+t  ], bl0 = Kl[n0][kk2+t  ];
                uint32_t bh1 = Kh[n0][kk2+t+4], bl1 = Kl[n0][kk2+t+4];
                #pragma unroll
                for(int mt = 0; mt < 2; mt++){
                    MMA3(S[mt][nt], ah[mt], al[mt], bh0, bh1, bl0, bl1);
                }
            }
        }
        float rmax[4] = {-1e30f,-1e30f,-1e30f,-1e30f};
        #pragma unroll
        for(int mt = 0; mt < 2; mt++)
        #pragma unroll
        for(int nt = 0; nt < 4; nt++)
        #pragma unroll
        for(int j = 0; j < 4; j++){
            float val = S[mt][nt][j]*0.125f;
            if(kt == ti){
                int row = wm*32 + mt*16 + g + ((j>>1)<<3);
                int col = wn*32 + nt*8 + 2*t + (j&1);
                if(col > row) val = -1e30f;
            }
            S[mt][nt][j] = val;
            int ri = mt*2 + (j>>1);
            rmax[ri] = fmaxf(rmax[ri], val);
        }
        #pragma unroll
        for(int i = 0; i < 4; i++){
            rmax[i] = fmaxf(rmax[i], __shfl_xor_sync(0xffffffffu, rmax[i], 1));
            rmax[i] = fmaxf(rmax[i], __shfl_xor_sync(0xffffffffu, rmax[i], 2));
        }
        if(t == 0){
            #pragma unroll
            for(int mt = 0; mt < 2; mt++){
                smax[wn][wm*32 + mt*16 + g    ] = rmax[mt*2];
                smax[wn][wm*32 + mt*16 + g + 8] = rmax[mt*2+1];
            }
        }
        __syncthreads();
        float mn[4], alp[4];
        #pragma unroll
        for(int mt = 0; mt < 2; mt++)
        #pragma unroll
        for(int rr = 0; rr < 2; rr++){
            int row = wm*32 + mt*16 + g + rr*8;
            float mm = fmaxf(smax[0][row], smax[1][row]);
            int i = mt*2 + rr;
            mn[i] = fmaxf(mo[i], mm);
            alp[i] = __expf(mo[i] - mn[i]);
            mo[i] = mn[i];
        }
        float rs[4] = {0.f,0.f,0.f,0.f};
        #pragma unroll
        for(int mt = 0; mt < 2; mt++)
        #pragma unroll
        for(int nt = 0; nt < 4; nt++)
        #pragma unroll
        for(int j = 0; j < 4; j++){
            int i = mt*2 + (j>>1);
            float e = __expf(S[mt][nt][j] - mn[i]);
            S[mt][nt][j] = e;
            rs[i] += e;
        }
        #pragma unroll
        for(int i = 0; i < 4; i++){
            rs[i] += __shfl_xor_sync(0xffffffffu, rs[i], 1);
            rs[i] += __shfl_xor_sync(0xffffffffu, rs[i], 2);
            l[i] = l[i]*alp[i] + rs[i];
        }
        #pragma unroll
        for(int mt = 0; mt < 2; mt++)
        #pragma unroll
        for(int n2 = 0; n2 < 8; n2++)
        #pragma unroll
        for(int j = 0; j < 4; j++)
            O[mt][n2][j] *= alp[mt*2 + (j>>1)];
        #pragma unroll
        for(int kg = 0; kg < 2; kg++){
            uint32_t ah[2][4], al[2][4];
            #pragma unroll
            for(int mt = 0; mt < 2; mt++){
                split2(S[mt][kg*2  ][0], S[mt][kg*2  ][1], ah[mt][0], al[mt][0]);
                split2(S[mt][kg*2  ][2], S[mt][kg*2  ][3], ah[mt][1], al[mt][1]);
                split2(S[mt][kg*2+1][0], S[mt][kg*2+1][1], ah[mt][2], al[mt][2]);
                split2(S[mt][kg*2+1][2], S[mt][kg*2+1][3], ah[mt][3], al[mt][3]);
            }
            int k2b = wn*16 + kg*8;
            #pragma unroll
            for(int n2 = 0; n2 < 8; n2++){
                int n0 = n2*8 + g;
                uint32_t bh0 = Vh[k2b+t  ][n0], bl0 = Vl[k2b+t  ][n0];
                uint32_t bh1 = Vh[k2b+t+4][n0], bl1 = Vl[k2b+t+4][n0];
                #pragma unroll
                for(int mt = 0; mt < 2; mt++){
                    MMA3(O[mt][n2], ah[mt], al[mt], bh0, bh1, bl0, bl1);
                }
            }
        }
    }
    __syncthreads();
    if(wn == 1){
        #pragma unroll
        for(int mt = 0; mt < 2; mt++)
        #pragma unroll
        for(int n2 = 0; n2 < 8; n2++)
        #pragma unroll
        for(int j = 0; j < 4; j++)
            sO[wm][lane][mt*32 + n2*4 + j] = O[mt][n2][j];
        #pragma unroll
        for(int i = 0; i < 4; i++) sO[wm][lane][64+i] = l[i];
    }
    __syncthreads();
    if(wn == 0){
        float inv[4];
        #pragma unroll
        for(int i = 0; i < 4; i++) inv[i] = 1.0f/(l[i] + sO[wm][lane][64+i]);
        #pragma unroll
        for(int mt = 0; mt < 2; mt++){
            int row0 = ti*64 + wm*32 + mt*16 + g;
            #pragma unroll
            for(int n2 = 0; n2 < 8; n2++){
                float o0 = (O[mt][n2][0] + sO[wm][lane][mt*32 + n2*4 + 0])*inv[mt*2];
                float o1 = (O[mt][n2][1] + sO[wm][lane][mt*32 + n2*4 + 1])*inv[mt*2];
                float o2 = (O[mt][n2][2] + sO[wm][lane][mt*32 + n2*4 + 2])*inv[mt*2+1];
                float o3 = (O[mt][n2][3] + sO[wm][lane][mt*32 + n2*4 + 3])*inv[mt*2+1];
                int col = n2*8 + 2*t;
                size_t w0 = ((size_t)(b*TT + row0))*512 + (h*64 + col)/2;
                size_t w1 = ((size_t)(b*TT + row0 + 8))*512 + (h*64 + col)/2;
                uint32_t hh, ll2;
                split2(o0, o1, hh, ll2); g_oh[w0] = hh; g_ol[w0] = ll2;
                split2(o2, o3, hh, ll2); g_oh[w1] = hh; g_ol[w1] = ll2;
            }
        }
    }
}

extern "C" void kernel_launch(void* const* d_in, const int* in_sizes, int n_in,
                              void* d_out, int out_size){
    const float* x         = (const float*)d_in[0];
    const float* summaries = (const float*)d_in[1];
    const float* ctx_w     = (const float*)d_in[2];
    const float* ctx_b     = (const float*)d_in[3];
    const float* base_adj  = (const float*)d_in[4];
    const float* warp_w    = (const float*)d_in[5];
    const float* warp_b    = (const float*)d_in[6];
    const float* gate_w    = (const float*)d_in[7];
    const float* gate_b    = (const float*)d_in[8];
    const float* g1_w      = (const float*)d_in[9];
    const float* g1_b      = (const float*)d_in[10];
    const float* g2_w      = (const float*)d_in[11];
    const float* g2_b      = (const float*)d_in[12];
    const float* ln1_g     = (const float*)d_in[13];
    const float* ln1_b     = (const float*)d_in[14];
    const float* wq        = (const float*)d_in[15];
    const float* bq        = (const float*)d_in[16];
    const float* wk        = (const float*)d_in[17];
    const float* bk        = (const float*)d_in[18];
    const float* wv        = (const float*)d_in[19];
    const float* bv        = (const float*)d_in[20];
    const float* wo        = (const float*)d_in[21];
    const float* bo        = (const float*)d_in[22];
    const float* ln2_g     = (const float*)d_in[23];
    const float* ln2_b     = (const float*)d_in[24];
    const float* ff1_w     = (const float*)d_in[25];
    const float* ff1_b     = (const float*)d_in[26];
    const float* ff2_w     = (const float*)d_in[27];
    const float* ff2_b     = (const float*)d_in[28];
    float* out = (float*)d_out;

    float *p_cur, *p_xo, *p_gate;
    uint32_t *p_oh,*p_ol,*p_nh,*p_nl,*p_mh,*p_ml,*p_wph,*p_wpl;
    cudaGetSymbolAddress((void**)&p_cur,  g_cur);
    cudaGetSymbolAddress((void**)&p_xo,   g_xo);
    cudaGetSymbolAddress((void**)&p_gate, g_gate);
    cudaGetSymbolAddress((void**)&p_oh, g_oh);  cudaGetSymbolAddress((void**)&p_ol, g_ol);
    cudaGetSymbolAddress((void**)&p_nh, g_normh); cudaGetSymbolAddress((void**)&p_nl, g_norml);
    cudaGetSymbolAddress((void**)&p_mh, g_midh); cudaGetSymbolAddress((void**)&p_ml, g_midl);
    cudaGetSymbolAddress((void**)&p_wph, g_wph); cudaGetSymbolAddress((void**)&p_wpl, g_wpl);

    cudaFuncSetAttribute(k_gemm3, cudaFuncAttributeMaxDynamicSharedMemorySize, DSMEM_BYTES);
    cudaFuncSetAttribute(k_qkv,   cudaFuncAttributeMaxDynamicSharedMemorySize, DSMEM_BYTES);

    // ---- router ----
    k_meanT_part<<<dim3(BB,32),256>>>(x);
    k_meanT_reduce<<<BB,256>>>();
    k_ctx<<<dim3(BB,32),128>>>(ctx_w, ctx_b);
    k_route1<<<dim3(BB,80),128>>>(warp_w, summaries, gate_w);
    k_route2<<<1,32>>>(base_adj, warp_b, gate_b,
                       out + BTD, out + BTD + 32, out + BTD + 32 + 256);

    // ---- 3 hops ----
    for(int hop = 0; hop < 3; hop++){
        const float* cin = (hop == 0) ? x : p_cur;
        float* cout = (hop == 2) ? out : p_cur;

        k_packw4<<<dim3(SZP/256,1,4),256>>>(wq, wk, wv, wo, p_wph, p_wpl, hop);
        k_packw<<<SZF/256,256>>>(ff1_w, p_wph+4*SZP,     p_wpl+4*SZP,     DFF, hop, (long)DD*DFF);
        k_packw<<<SZF/256,256>>>(ff2_w, p_wph+4*SZP+SZF, p_wpl+4*SZP+SZF, DD,  hop, (long)DFF*DD);

        if(hop > 0){
            k_meanT_part<<<dim3(BB,32),256>>>(cin);
            k_meanT_reduce<<<BB,256>>>();
        }
        k_g1<<<dim3(BB,16),256>>>(g1_w, g1_b, hop);
        k_g2<<<1,256>>>(g2_w, g2_b, hop);
        k_ln2<<<BT,256>>>(cin, ln1_g, ln1_b, hop, p_gate, p_nh, p_nl);
        k_qkv<<<dim3(8,32,3),256,DSMEM_BYTES>>>(p_nh, p_nl, p_wph, p_wpl, bq, bk, bv, hop);
        k_flash<<<dim3(16,BB*HH),128>>>();
        k_gemm3<<<dim3(8,32),256,DSMEM_BYTES>>>(p_oh,p_ol, p_wph+3*SZP,p_wpl+3*SZP, bo, DD, hop,
                                    cin, p_gate, nullptr, p_xo, nullptr,nullptr, DD, DD, 0, 0);
        k_ln2<<<BT,256>>>(p_xo, ln2_g, ln2_b, hop, nullptr, p_nh, p_nl);
        k_gemm3<<<dim3(32,32),256,DSMEM_BYTES>>>(p_nh,p_nl, p_wph+4*SZP,p_wpl+4*SZP, ff1_b, DFF, hop,
                                    nullptr,nullptr,nullptr, nullptr, p_mh,p_ml, DFF, DD, 1, 1);
        k_gemm3<<<dim3(8,32),256,DSMEM_BYTES>>>(p_mh,p_ml, p_wph+4*SZP+SZF,p_wpl+4*SZP+SZF, ff2_b, DD, hop,
                                    p_xo, nullptr, cin, cout, nullptr,nullptr, DD, DFF, 0, 2);
    }
}

// round 15
// speedup vs baseline: 1.1664x; 1.0059x over previous
#include <cuda_runtime.h>
#include <cuda_bf16.h>
#include <math.h>
#include <stdint.h>

#define BB 4
#define TT 1024
#define DD 1024
#define HH 16
#define DFF 4096
#define RR 8
#define BT (BB*TT)
#define BTD (BB*TT*DD)
#define SZP (512*1024)
#define SZF 2097152
#define WHOP (4*SZP + 2*SZF)      // packed words per hop

// ---------------- device scratch ----------------
__device__ float g_cur[BTD];
__device__ float g_xo[BTD];
__device__ uint32_t g_qh[BT*512], g_ql[BT*512];
__device__ uint32_t g_kh[BT*512], g_kl[BT*512];
__device__ uint32_t g_vh[BB*HH*512*64], g_vl[BB*HH*512*64];
__device__ uint32_t g_oh[BT*512], g_ol[BT*512];
__device__ uint32_t g_normh[BT*512], g_norml[BT*512];
__device__ uint32_t g_midh[BT*2048], g_midl[BT*2048];
__device__ uint32_t g_wph[3*WHOP], g_wpl[3*WHOP];
__device__ float g_part[BB*32*DD];
__device__ float g_ctxm[BB*DD];
__device__ float g_ctx[BB*DD];
__device__ float g_rt[BB*80];
__device__ float g_h1[BB*256];
__device__ float g_gate[BB];
__device__ float g_gm;
__device__ int   g_idx[3];

__device__ __forceinline__ float geluf(float x){
    return 0.5f*x*(1.0f+erff(x*0.7071067811865476f));
}
__device__ __forceinline__ void split2(float x, float y, uint32_t &hi, uint32_t &lo){
    __nv_bfloat16 xh = __float2bfloat16_rn(x);
    __nv_bfloat16 yh = __float2bfloat16_rn(y);
    __nv_bfloat162 h; h.x = xh; h.y = yh;
    __nv_bfloat162 l; l.x = __float2bfloat16_rn(x - __bfloat162float(xh));
    l.y = __float2bfloat16_rn(y - __bfloat162float(yh));
    hi = *(uint32_t*)&h; lo = *(uint32_t*)&l;
}
__device__ __forceinline__ void mma_bf16(float* c, uint32_t a0, uint32_t a1, uint32_t a2, uint32_t a3,
                                         uint32_t b0, uint32_t b1){
    asm volatile("mma.sync.aligned.m16n8k16.row.col.f32.bf16.bf16.f32 "
        "{%0,%1,%2,%3},{%4,%5,%6,%7},{%8,%9},{%0,%1,%2,%3};"
        : "+f"(c[0]), "+f"(c[1]), "+f"(c[2]), "+f"(c[3])
        : "r"(a0), "r"(a1), "r"(a2), "r"(a3), "r"(b0), "r"(b1));
}
#define MMA3(accp, AH, AL, BH0, BH1, BL0, BL1) \
    mma_bf16(accp, AH[0],AH[1],AH[2],AH[3], BH0, BH1); \
    mma_bf16(accp, AH[0],AH[1],AH[2],AH[3], BL0, BL1); \
    mma_bf16(accp, AL[0],AL[1],AL[2],AL[3], BH0, BH1);

__device__ __forceinline__ void cpa16(void* dst, const void* src){
    uint32_t d = (uint32_t)__cvta_generic_to_shared(dst);
    asm volatile("cp.async.cg.shared.global [%0], [%1], 16;" :: "r"(d), "l"(src));
}
#define CP_COMMIT() asm volatile("cp.async.commit_group;")

// ---------------- small kernels ----------------
__global__ void k_meanT_part(const float* __restrict__ in){
    int b = blockIdx.x, c = blockIdx.y;
    int t0 = c*32;
    for(int d = threadIdx.x; d < DD; d += 256){
        float s = 0.f;
        for(int t = t0; t < t0+32; t++) s += in[((size_t)(b*TT+t))*DD + d];
        g_part[(size_t)(b*32+c)*DD + d] = s;
    }
}
__global__ void k_meanT_reduce(){
    int b = blockIdx.x;
    for(int d = threadIdx.x; d < DD; d += 256){
        float s = 0.f;
        for(int c = 0; c < 32; c++) s += g_part[(size_t)(b*32+c)*DD + d];
        g_ctxm[b*DD + d] = s*(1.0f/TT);
    }
}
__global__ void k_ctx(const float* __restrict__ W, const float* __restrict__ bias){
    int b = blockIdx.x; int n0 = blockIdx.y*32;
    int lane = threadIdx.x & 31, q = threadIdx.x >> 5;
    const float* xv = &g_ctxm[b*DD];
    float s = 0.f;
    int k0 = q*256;
    for(int k = k0; k < k0+256; k++) s += xv[k]*W[(size_t)k*DD + n0 + lane];
    __shared__ float red[4][32];
    red[q][lane] = s; __syncthreads();
    if(q == 0)
        g_ctx[b*DD + n0 + lane] = red[0][lane]+red[1][lane]+red[2][lane]+red[3][lane] + bias[n0+lane];
}
__global__ void __launch_bounds__(128) k_route1(const float* __restrict__ warp_w,
        const float* __restrict__ summaries, const float* __restrict__ gate_w){
    int b = blockIdx.x, o = blockIdx.y;
    int tid = threadIdx.x;
    const float* xv = &g_ctx[b*DD];
    float s = 0.f;
    if(o < 64){
        for(int k = tid; k < DD; k += 128) s += xv[k]*warp_w[(size_t)k*64 + o];
    } else if(o < 72){
        const float* sr = summaries + (size_t)(o-64)*DD;
        for(int k = tid; k < DD; k += 128) s += xv[k]*sr[k];
    } else {
        for(int k = tid; k < DD; k += 128) s += xv[k]*gate_w[k*RR + (o-72)];
    }
    __shared__ float red[128];
    red[tid] = s; __syncthreads();
    for(int off = 64; off >= 1; off >>= 1){
        if(tid < off) red[tid] += red[tid+off];
        __syncthreads();
    }
    if(tid == 0) g_rt[b*80 + o] = red[0];
}
__global__ void k_route2(const float* __restrict__ base_adj,
                         const float* __restrict__ warp_b, const float* __restrict__ gate_b,
                         float* __restrict__ out_gs, float* __restrict__ out_adj,
                         float* __restrict__ out_mh){
    __shared__ float s_gs[BB][RR];
    int tid = threadIdx.x;
    if(tid < 32){
        int b = tid/8, i = tid%8;
        float v[8]; float mx = -1e30f;
        for(int j = 0; j < 8; j++){
            v[j] = base_adj[i*8+j] + (g_rt[b*80 + i*8 + j] + warp_b[i*8+j])*0.1f;
            mx = fmaxf(mx, v[j]);
        }
        float sum = 0.f;
        for(int j = 0; j < 8; j++){ v[j] = expf(v[j]-mx); sum += v[j]; }
        float inv = 1.0f/sum;
        float boost = 0.f;
        for(int j = 0; j < 8; j++){
            float a = v[j]*inv;
            out_adj[(b*8+i)*8 + j] = a;
            boost += a*g_rt[b*80 + 64 + j];
        }
        float gl = g_rt[b*80 + 72 + i] + gate_b[i];
        float gs = 1.0f/(1.0f+expf(-(gl+boost)*0.5f));
        out_gs[b*8+i] = gs;
        s_gs[b][i] = gs;
    }
    __syncthreads();
    if(tid == 0){
        float m[RR];
        for(int r = 0; r < 8; r++) m[r] = 0.25f*(s_gs[0][r]+s_gs[1][r]+s_gs[2][r]+s_gs[3][r]);
        for(int h = 0; h < 3; h++){
            int best = 0; float bv = -1e30f;
            for(int r = 0; r < 8; r++) if(m[r] > bv){ bv = m[r]; best = r; }
            g_idx[h] = best; m[best] = -1e30f;
        }
        out_mh[0] = 3.0f;
    }
}
__global__ void __launch_bounds__(256) k_g1(const float* __restrict__ g1_w, const float* __restrict__ g1_b, int hop){
    int room = g_idx[hop];
    int b = blockIdx.x;
    int tid = threadIdx.x;
    int n = blockIdx.y*16 + (tid & 15);
    int slice = tid >> 4;
    const float* W = g1_w + (size_t)room*DD*256;
    const float* xv = &g_ctxm[b*DD];
    float s = 0.f;
    int k0 = slice*64;
    for(int k = k0; k < k0+64; k++) s += xv[k]*W[(size_t)k*256 + n];
    __shared__ float red[256];
    red[tid] = s; __syncthreads();
    if(tid < 16){
        float tot = 0.f;
        for(int sl = 0; sl < 16; sl++) tot += red[tid + 16*sl];
        int nn = blockIdx.y*16 + tid;
        g_h1[b*256 + nn] = geluf(tot + g1_b[room*256 + nn]);
    }
}
__global__ void k_g2(const float* __restrict__ g2_w, const float* __restrict__ g2_b, int hop){
    int room = g_idx[hop];
    __shared__ float red[256];
    int tid = threadIdx.x;
    int b = tid/64, lane = tid%64;
    const float* W = g2_w + room*256;
    float s = 0.f;
    for(int k = lane; k < 256; k += 64) s += g_h1[b*256 + k]*W[k];
    red[tid] = s; __syncthreads();
    for(int off = 32; off >= 1; off >>= 1){
        if(lane < off) red[tid] += red[tid+off];
        __syncthreads();
    }
    if(lane == 0){
        float gate = 1.0f/(1.0f+expf(-(red[tid]+g2_b[room])));
        g_gate[b] = gate;
    }
    __syncthreads();
    if(tid == 0) g_gm = 0.25f*(g_gate[0]+g_gate[1]+g_gate[2]+g_gate[3]);
}

// mega-pack: ALL 3 hops x 6 weights in one launch. Layout per hop matches GEMM consumers:
// [q(SZP), k(SZP), v(SZP), wo(SZP), ff1(SZF), ff2(SZF)] vertical k-pairs [K/2][N]
__global__ void __launch_bounds__(256) k_packall(
        const float* __restrict__ wq, const float* __restrict__ wk,
        const float* __restrict__ wv, const float* __restrict__ wo,
        const float* __restrict__ ff1, const float* __restrict__ ff2){
    size_t i = (size_t)blockIdx.x*256 + threadIdx.x;
    int hop = (int)(i / WHOP);
    size_t j = i % WHOP;
    int room = g_idx[hop];
    const float* W; int N;
    size_t jj;
    if(j < (size_t)4*SZP){
        int z = (int)(j / SZP); jj = j % SZP;
        const float* Wb = (z==0) ? wq : (z==1) ? wk : (z==2) ? wv : wo;
        W = Wb + (size_t)room*DD*DD; N = DD;
    } else {
        size_t j2 = j - (size_t)4*SZP;
        int z = (int)(j2 / SZF); jj = j2 % SZF;
        if(z == 0){ W = ff1 + (size_t)room*DD*DFF; N = DFF; }
        else      { W = ff2 + (size_t)room*DFF*DD; N = DD; }
    }
    size_t k2 = jj / N, n = jj % N;
    float a = W[(2*k2)*N + n];
    float b = W[(2*k2+1)*N + n];
    uint32_t hh, ll; split2(a, b, hh, ll);
    g_wph[i] = hh; g_wpl[i] = ll;
}

// layernorm -> split bf16 planes
__global__ void __launch_bounds__(256) k_ln2(const float* __restrict__ in,
                     const float* __restrict__ gb, const float* __restrict__ bb,
                     int hop, const float* __restrict__ gate,
                     uint32_t* __restrict__ oh, uint32_t* __restrict__ ol){
    int row = blockIdx.x; int b = row >> 10;
    int room = g_idx[hop];
    float sc = gate ? gate[b] : 1.0f;
    float4 v = ((const float4*)(in + (size_t)row*DD))[threadIdx.x];
    v.x *= sc; v.y *= sc; v.z *= sc; v.w *= sc;
    __shared__ float rs[256], rq[256];
    rs[threadIdx.x] = v.x+v.y+v.z+v.w;
    rq[threadIdx.x] = v.x*v.x+v.y*v.y+v.z*v.z+v.w*v.w;
    __syncthreads();
    for(int off = 128; off >= 1; off >>= 1){
        if(threadIdx.x < off){ rs[threadIdx.x] += rs[threadIdx.x+off]; rq[threadIdx.x] += rq[threadIdx.x+off]; }
        __syncthreads();
    }
    float mean = rs[0]*(1.0f/DD);
    float var  = rq[0]*(1.0f/DD) - mean*mean;
    float inv  = rsqrtf(var + 1e-5f);
    float4 g4 = ((const float4*)(gb + (size_t)room*DD))[threadIdx.x];
    float4 b4 = ((const float4*)(bb + (size_t)room*DD))[threadIdx.x];
    float o0 = (v.x-mean)*inv*g4.x + b4.x;
    float o1 = (v.y-mean)*inv*g4.y + b4.y;
    float o2 = (v.z-mean)*inv*g4.z + b4.z;
    float o3 = (v.w-mean)*inv*g4.w + b4.w;
    uint32_t h0,l0,h1,l1;
    split2(o0,o1,h0,l0); split2(o2,o3,h1,l1);
    size_t w = (size_t)row*512 + threadIdx.x*2;
    *(uint2*)&oh[w] = make_uint2(h0,h1);
    *(uint2*)&ol[w] = make_uint2(l0,l1);
}

// ---------------- GEMM core: BK=32, 3-stage cp.async ring (frozen R9/R12 config) ----------------
#define SA_OFF(s,r,c) ((s)*2560 + (r)*20 + (c))
#define SB_OFF(s,k,c) ((s)*2176 + (k)*136 + (c))
#define DSMEM_BYTES ((7680*2 + 6528*2)*4)

__device__ __forceinline__ void gemm_core(
        const uint32_t* __restrict__ Ah, const uint32_t* __restrict__ Al,
        const uint32_t* __restrict__ Wh, const uint32_t* __restrict__ Wl,
        int N, int K, int bm, int bn,
        uint32_t* sAh, uint32_t* sAl, uint32_t* sBh, uint32_t* sBl,
        float acc[2][8][4], int tid, int wm, int wn, int g, int t){
    int halfK = K >> 1;
    int nC = K >> 5;
    int arA = tid>>2, acA = (tid&3)*4;
    int brA = tid>>5, bcA = (tid&31)*4;
    const uint32_t* AhS = Ah + (size_t)(bm*128 + arA)*halfK + acA;
    const uint32_t* AlS = Al + (size_t)(bm*128 + arA)*halfK + acA;
    const uint32_t* WhS = Wh + (size_t)brA*N + bn*128 + bcA;
    const uint32_t* WlS = Wl + (size_t)brA*N + bn*128 + bcA;
    const size_t a64 = (size_t)64*halfK;
    const size_t b8  = (size_t)8*N;

    #pragma unroll
    for(int s = 0; s < 2; s++){
        if(s < nC){
            int k0w = s*16;
            cpa16(sAh + SA_OFF(s,arA,acA), AhS + k0w);
            cpa16(sAh + SA_OFF(s,arA+64,acA), AhS + a64 + k0w);
            cpa16(sAl + SA_OFF(s,arA,acA), AlS + k0w);
            cpa16(sAl + SA_OFF(s,arA+64,acA), AlS + a64 + k0w);
            cpa16(sBh + SB_OFF(s,brA,bcA), WhS + (size_t)k0w*N);
            cpa16(sBh + SB_OFF(s,brA+8,bcA), WhS + (size_t)k0w*N + b8);
            cpa16(sBl + SB_OFF(s,brA,bcA), WlS + (size_t)k0w*N);
            cpa16(sBl + SB_OFF(s,brA+8,bcA), WlS + (size_t)k0w*N + b8);
            CP_COMMIT();
        }
    }
    for(int c = 0; c < nC; c++){
        if(c+1 < nC) asm volatile("cp.async.wait_group 1;");
        else         asm volatile("cp.async.wait_group 0;");
        __syncthreads();
        if(c+2 < nC){
            int s = (c+2)%3;
            int k0w = (c+2)*16;
            cpa16(sAh + SA_OFF(s,arA,acA), AhS + k0w);
            cpa16(sAh + SA_OFF(s,arA+64,acA), AhS + a64 + k0w);
            cpa16(sAl + SA_OFF(s,arA,acA), AlS + k0w);
            cpa16(sAl + SA_OFF(s,arA+64,acA), AlS + a64 + k0w);
            cpa16(sBh + SB_OFF(s,brA,bcA), WhS + (size_t)k0w*N);
            cpa16(sBh + SB_OFF(s,brA+8,bcA), WhS + (size_t)k0w*N + b8);
            cpa16(sBl + SB_OFF(s,brA,bcA), WlS + (size_t)k0w*N);
            cpa16(sBl + SB_OFF(s,brA+8,bcA), WlS + (size_t)k0w*N + b8);
            CP_COMMIT();
        }
        int cb = c%3;
        #pragma unroll
        for(int kk2 = 0; kk2 < 16; kk2 += 8){
            uint32_t ah[2][4], al[2][4];
            #pragma unroll
            for(int mt = 0; mt < 2; mt++){
                int m0 = wm*32 + mt*16;
                ah[mt][0] = sAh[SA_OFF(cb,m0+g  ,kk2+t  )]; al[mt][0] = sAl[SA_OFF(cb,m0+g  ,kk2+t  )];
                ah[mt][1] = sAh[SA_OFF(cb,m0+g+8,kk2+t  )]; al[mt][1] = sAl[SA_OFF(cb,m0+g+8,kk2+t  )];
                ah[mt][2] = sAh[SA_OFF(cb,m0+g  ,kk2+t+4)]; al[mt][2] = sAl[SA_OFF(cb,m0+g  ,kk2+t+4)];
                ah[mt][3] = sAh[SA_OFF(cb,m0+g+8,kk2+t+4)]; al[mt][3] = sAl[SA_OFF(cb,m0+g+8,kk2+t+4)];
            }
            #pragma unroll
            for(int nt = 0; nt < 8; nt++){
                int n0 = wn*64 + nt*8 + g;
                uint32_t bh0 = sBh[SB_OFF(cb,kk2+t  ,n0)], bl0 = sBl[SB_OFF(cb,kk2+t  ,n0)];
                uint32_t bh1 = sBh[SB_OFF(cb,kk2+t+4,n0)], bl1 = sBl[SB_OFF(cb,kk2+t+4,n0)];
                #pragma unroll
                for(int mt = 0; mt < 2; mt++){
                    MMA3(acc[mt][nt], ah[mt], al[mt], bh0, bh1, bl0, bl1);
                }
            }
        }
        __syncthreads();
    }
}

// generic GEMM: mode 0: f32 (+res*rscale); mode 1: split planes (opt gelu); mode 2: fused mix
__global__ void __launch_bounds__(256,2) k_gemm3(
        const uint32_t* __restrict__ Ah, const uint32_t* __restrict__ Al,
        const uint32_t* __restrict__ Wh, const uint32_t* __restrict__ Wl,
        const float* __restrict__ bbase, long bstr, int hop,
        const float* __restrict__ res, const float* __restrict__ rscale,
        const float* __restrict__ curin,
        float* __restrict__ C, uint32_t* __restrict__ Ch, uint32_t* __restrict__ Cl,
        int N, int K, int act, int mode){
    extern __shared__ uint32_t smem_u[];
    uint32_t* sAh = smem_u;
    uint32_t* sAl = sAh + 7680;
    uint32_t* sBh = sAl + 7680;
    uint32_t* sBl = sBh + 6528;
    int room = g_idx[hop];
    const float* bias = bbase + (size_t)room*bstr;
    int tid = threadIdx.x;
    int bm = blockIdx.y, bn = blockIdx.x;
    int warp = tid>>5, lane = tid&31;
    int g = lane>>2, t = lane&3;
    int wm = warp>>1, wn = warp&1;

    float acc[2][8][4] = {};
    gemm_core(Ah, Al, Wh, Wl, N, K, bm, bn, sAh, sAl, sBh, sBl, acc, tid, wm, wn, g, t);

    float gm = (mode == 2) ? g_gm : 0.f;
    #pragma unroll
    for(int mt = 0; mt < 2; mt++){
        int row = bm*128 + wm*32 + mt*16 + g;
        #pragma unroll
        for(int nt = 0; nt < 8; nt++){
            int col = bn*128 + wn*64 + nt*8 + 2*t;
            float2 bi = *(const float2*)&bias[col];
            float v0 = acc[mt][nt][0] + bi.x;
            float v1 = acc[mt][nt][1] + bi.y;
            float v2 = acc[mt][nt][2] + bi.x;
            float v3 = acc[mt][nt][3] + bi.y;
            if(act == 1){
                v0 = geluf(v0); v1 = geluf(v1); v2 = geluf(v2); v3 = geluf(v3);
            }
            size_t i0 = (size_t)row*N + col, i1 = (size_t)(row+8)*N + col;
            if(mode == 0){
                if(res){
                    float sc = rscale ? rscale[row>>10] : 1.0f;
                    float2 r0 = *(const float2*)&res[i0];
                    float2 r1 = *(const float2*)&res[i1];
                    v0 += r0.x*sc; v1 += r0.y*sc; v2 += r1.x*sc; v3 += r1.y*sc;
                }
                *(float2*)&C[i0] = make_float2(v0, v1);
                *(float2*)&C[i1] = make_float2(v2, v3);
            } else if(mode == 1){
                uint32_t hh, ll;
                size_t w0 = (size_t)row*(N>>1) + (col>>1);
                size_t w1 = (size_t)(row+8)*(N>>1) + (col>>1);
                split2(v0, v1, hh, ll); Ch[w0] = hh; Cl[w0] = ll;
                split2(v2, v3, hh, ll); Ch[w1] = hh; Cl[w1] = ll;
            } else {
                float2 r0 = *(const float2*)&res[i0];
                float2 r1 = *(const float2*)&res[i1];
                float2 c0 = *(const float2*)&curin[i0];
                float2 c1 = *(const float2*)&curin[i1];
                float x0 = r0.x + v0, x1 = r0.y + v1, x2 = r1.x + v2, x3 = r1.y + v3;
                *(float2*)&C[i0] = make_float2(c0.x + gm*(x0-c0.x), c0.y + gm*(x1-c0.y));
                *(float2*)&C[i1] = make_float2(c1.x + gm*(x2-c1.x), c1.y + gm*(x3-c1.y));
            }
        }
    }
}

// batched QKV: grid (8,32,3). z=0 -> q planes, z=1 -> k planes, z=2 -> V planes (fused vsplit)
__global__ void __launch_bounds__(256,2) k_qkv(
        const uint32_t* __restrict__ Ah, const uint32_t* __restrict__ Al,
        const uint32_t* __restrict__ Wp_h, const uint32_t* __restrict__ Wp_l,
        const float* __restrict__ bq, const float* __restrict__ bk_,
        const float* __restrict__ bv, int hop){
    extern __shared__ uint32_t smem_u[];
    uint32_t* sAh = smem_u;
    uint32_t* sAl = sAh + 7680;
    uint32_t* sBh = sAl + 7680;
    uint32_t* sBl = sBh + 6528;
    int room = g_idx[hop];
    int z = blockIdx.z;
    const float* bias = (z==0 ? bq : (z==1 ? bk_ : bv)) + (size_t)room*DD;
    const uint32_t* Wh = Wp_h + (size_t)z*SZP;
    const uint32_t* Wl = Wp_l + (size_t)z*SZP;
    int tid = threadIdx.x;
    int bm = blockIdx.y, bn = blockIdx.x;
    int warp = tid>>5, lane = tid&31;
    int g = lane>>2, t = lane&3;
    int wm = warp>>1, wn = warp&1;

    float acc[2][8][4] = {};
    gemm_core(Ah, Al, Wh, Wl, DD, DD, bm, bn, sAh, sAl, sBh, sBl, acc, tid, wm, wn, g, t);

    uint32_t* Ch = (z==0) ? g_qh : g_kh;
    uint32_t* Cl = (z==0) ? g_ql : g_kl;
    #pragma unroll
    for(int mt = 0; mt < 2; mt++){
        int row = bm*128 + wm*32 + mt*16 + g;
        #pragma unroll
        for(int nt = 0; nt < 8; nt++){
            int col = bn*128 + wn*64 + nt*8 + 2*t;
            float2 bi = *(const float2*)&bias[col];
            float v0 = acc[mt][nt][0] + bi.x;
            float v1 = acc[mt][nt][1] + bi.y;
            float v2 = acc[mt][nt][2] + bi.x;
            float v3 = acc[mt][nt][3] + bi.y;
            if(z == 2){
                float p0 = __shfl_xor_sync(0xffffffffu, v0, 4);
                float p1 = __shfl_xor_sync(0xffffffffu, v1, 4);
                float p2 = __shfl_xor_sync(0xffffffffu, v2, 4);
                float p3 = __shfl_xor_sync(0xffffffffu, v3, 4);
                if((g & 1) == 0){
                    int b = row >> 10;
                    int h = col >> 6, dh = col & 63;
                    int k2a = (row & (TT-1)) >> 1;
                    int k2b = ((row + 8) & (TT-1)) >> 1;
                    uint32_t h0,l0,h1,l1;
                    size_t oa = ((size_t)(b*HH + h)*512 + k2a)*64 + dh;
                    size_t ob = ((size_t)(b*HH + h)*512 + k2b)*64 + dh;
                    split2(v0, p0, h0, l0); split2(v1, p1, h1, l1);
                    *(uint2*)(g_vh + oa) = make_uint2(h0, h1);
                    *(uint2*)(g_vl + oa) = make_uint2(l0, l1);
                    split2(v2, p2, h0, l0); split2(v3, p3, h1, l1);
                    *(uint2*)(g_vh + ob) = make_uint2(h0, h1);
                    *(uint2*)(g_vl + ob) = make_uint2(l0, l1);
                }
            } else {
                uint32_t hh, ll;
                size_t w0 = (size_t)row*512 + (col>>1);
                size_t w1 = (size_t)(row+8)*512 + (col>>1);
                split2(v0, v1, hh, ll); Ch[w0] = hh; Cl[w0] = ll;
                split2(v2, v3, hh, ll); Ch[w1] = hh; Cl[w1] = ll;
            }
        }
    }
}

// ---------------- fused flash attention (bf16x3, online softmax) ----------------
__global__ void __launch_bounds__(128) k_flash(){
    int ti = 15 - (int)blockIdx.x;
    int bh = blockIdx.y; int b = bh>>4, h = bh&15;
    __shared__ uint32_t Qh[64][36], Ql[64][36];
    __shared__ uint32_t Kh[64][36], Kl[64][36];
    __shared__ uint32_t Vh[32][72], Vl[32][72];
    __shared__ float smax[2][64];
    __shared__ float sO[2][32][68];
    int tid = threadIdx.x;
    int warp = tid>>5, lane = tid&31;
    int g = lane>>2, t = lane&3;
    int wm = warp>>1, wn = warp&1;
    int vk2 = tid>>4, vn4 = tid&15;

    #pragma unroll
    for(int i = 0; i < 4; i++){
        int idx = tid + 128*i;
        int r = idx>>3, c = (idx&7)*4;
        size_t qoff = ((size_t)(b*TT + ti*64 + r))*512 + h*32 + c;
        *(uint4*)&Qh[r][c] = *(const uint4*)(g_qh + qoff);
        *(uint4*)&Ql[r][c] = *(const uint4*)(g_ql + qoff);
    }

    float mo[4], l[4], O[2][8][4];
    #pragma unroll
    for(int i = 0; i < 4; i++){ mo[i] = -1e30f; l[i] = 0.f; }
    #pragma unroll
    for(int a = 0; a < 2; a++)
        #pragma unroll
        for(int n2 = 0; n2 < 8; n2++)
            #pragma unroll
            for(int j = 0; j < 4; j++) O[a][n2][j] = 0.f;

    for(int kt = 0; kt <= ti; kt++){
        __syncthreads();
        #pragma unroll
        for(int i = 0; i < 4; i++){
            int idx = tid + 128*i;
            int r = idx>>3, c = (idx&7)*4;
            size_t koff = ((size_t)(b*TT + kt*64 + r))*512 + h*32 + c;
            *(uint4*)&Kh[r][c] = *(const uint4*)(g_kh + koff);
            *(uint4*)&Kl[r][c] = *(const uint4*)(g_kl + koff);
        }
        #pragma unroll
        for(int i = 0; i < 4; i++){
            int k2 = vk2 + 8*i;
            size_t voff = ((size_t)bh*512 + kt*32 + k2)*64 + vn4*4;
            *(uint4*)&Vh[k2][vn4*4] = *(const uint4*)(g_vh + voff);
            *(uint4*)&Vl[k2][vn4*4] = *(const uint4*)(g_vl + voff);
        }
        __syncthreads();

        float S[2][4][4];
        #pragma unroll
        for(int a = 0; a < 2; a++)
            #pragma unroll
            for(int n = 0; n < 4; n++)
                #pragma unroll
                for(int c = 0; c < 4; c++) S[a][n][c] = 0.f;
        #pragma unroll
        for(int kk2 = 0; kk2 < 32; kk2 += 8){
            uint32_t ah[2][4], al[2][4];
            #pragma unroll
            for(int mt = 0; mt < 2; mt++){
                int m0 = wm*32 + mt*16;
                ah[mt][0] = Qh[m0+g  ][kk2+t  ]; al[mt][0] = Ql[m0+g  ][kk2+t  ];
                ah[mt][1] = Qh[m0+g+8][kk2+t  ]; al[mt][1] = Ql[m0+g+8][kk2+t  ];
                ah[mt][2] = Qh[m0+g  ][kk2+t+4]; al[mt][2] = Ql[m0+g  ][kk2+t+4];
                ah[mt][3] = Qh[m0+g+8][kk2+t+4]; al[mt][3] = Ql[m0+g+8][kk2+t+4];
            }
            #pragma unroll
            for(int nt = 0; nt < 4; nt++){
                int n0 = wn*32 + nt*8 + g;
                uint32_t bh0 = Kh[n0][kk2+t  ], bl0 = Kl[n0][kk2+t  ];
                uint32_t bh1 = Kh[n0][kk2+t+4], bl1 = Kl[n0][kk2+t+4];
                #pragma unroll
                for(int mt = 0; mt < 2; mt++){
                    MMA3(S[mt][nt], ah[mt], al[mt], bh0, bh1, bl0, bl1);
                }
            }
        }
        float rmax[4] = {-1e30f,-1e30f,-1e30f,-1e30f};
        #pragma unroll
        for(int mt = 0; mt < 2; mt++)
        #pragma unroll
        for(int nt = 0; nt < 4; nt++)
        #pragma unroll
        for(int j = 0; j < 4; j++){
            float val = S[mt][nt][j]*0.125f;
            if(kt == ti){
                int row = wm*32 + mt*16 + g + ((j>>1)<<3);
                int col = wn*32 + nt*8 + 2*t + (j&1);
                if(col > row) val = -1e30f;
            }
            S[mt][nt][j] = val;
            int ri = mt*2 + (j>>1);
            rmax[ri] = fmaxf(rmax[ri], val);
        }
        #pragma unroll
        for(int i = 0; i < 4; i++){
            rmax[i] = fmaxf(rmax[i], __shfl_xor_sync(0xffffffffu, rmax[i], 1));
            rmax[i] = fmaxf(rmax[i], __shfl_xor_sync(0xffffffffu, rmax[i], 2));
        }
        if(t == 0){
            #pragma unroll
            for(int mt = 0; mt < 2; mt++){
                smax[wn][wm*32 + mt*16 + g    ] = rmax[mt*2];
                smax[wn][wm*32 + mt*16 + g + 8] = rmax[mt*2+1];
            }
        }
        __syncthreads();
        float mn[4], alp[4];
        #pragma unroll
        for(int mt = 0; mt < 2; mt++)
        #pragma unroll
        for(int rr = 0; rr < 2; rr++){
            int row = wm*32 + mt*16 + g + rr*8;
            float mm = fmaxf(smax[0][row], smax[1][row]);
            int i = mt*2 + rr;
            mn[i] = fmaxf(mo[i], mm);
            alp[i] = __expf(mo[i] - mn[i]);
            mo[i] = mn[i];
        }
        float rs[4] = {0.f,0.f,0.f,0.f};
        #pragma unroll
        for(int mt = 0; mt < 2; mt++)
        #pragma unroll
        for(int nt = 0; nt < 4; nt++)
        #pragma unroll
        for(int j = 0; j < 4; j++){
            int i = mt*2 + (j>>1);
            float e = __expf(S[mt][nt][j] - mn[i]);
            S[mt][nt][j] = e;
            rs[i] += e;
        }
        #pragma unroll
        for(int i = 0; i < 4; i++){
            rs[i] += __shfl_xor_sync(0xffffffffu, rs[i], 1);
            rs[i] += __shfl_xor_sync(0xffffffffu, rs[i], 2);
            l[i] = l[i]*alp[i] + rs[i];
        }
        #pragma unroll
        for(int mt = 0; mt < 2; mt++)
        #pragma unroll
        for(int n2 = 0; n2 < 8; n2++)
        #pragma unroll
        for(int j = 0; j < 4; j++)
            O[mt][n2][j] *= alp[mt*2 + (j>>1)];
        #pragma unroll
        for(int kg = 0; kg < 2; kg++){
            uint32_t ah[2][4], al[2][4];
            #pragma unroll
            for(int mt = 0; mt < 2; mt++){
                split2(S[mt][kg*2  ][0], S[mt][kg*2  ][1], ah[mt][0], al[mt][0]);
                split2(S[mt][kg*2  ][2], S[mt][kg*2  ][3], ah[mt][1], al[mt][1]);
                split2(S[mt][kg*2+1][0], S[mt][kg*2+1][1], ah[mt][2], al[mt][2]);
                split2(S[mt][kg*2+1][2], S[mt][kg*2+1][3], ah[mt][3], al[mt][3]);
            }
            int k2b = wn*16 + kg*8;
            #pragma unroll
            for(int n2 = 0; n2 < 8; n2++){
                int n0 = n2*8 + g;
                uint32_t bh0 = Vh[k2b+t  ][n0], bl0 = Vl[k2b+t  ][n0];
                uint32_t bh1 = Vh[k2b+t+4][n0], bl1 = Vl[k2b+t+4][n0];
                #pragma unroll
                for(int mt = 0; mt < 2; mt++){
                    MMA3(O[mt][n2], ah[mt], al[mt], bh0, bh1, bl0, bl1);
                }
            }
        }
    }
    __syncthreads();
    if(wn == 1){
        #pragma unroll
        for(int mt = 0; mt < 2; mt++)
        #pragma unroll
        for(int n2 = 0; n2 < 8; n2++)
        #pragma unroll
        for(int j = 0; j < 4; j++)
            sO[wm][lane][mt*32 + n2*4 + j] = O[mt][n2][j];
        #pragma unroll
        for(int i = 0; i < 4; i++) sO[wm][lane][64+i] = l[i];
    }
    __syncthreads();
    if(wn == 0){
        float inv[4];
        #pragma unroll
        for(int i = 0; i < 4; i++) inv[i] = 1.0f/(l[i] + sO[wm][lane][64+i]);
        #pragma unroll
        for(int mt = 0; mt < 2; mt++){
            int row0 = ti*64 + wm*32 + mt*16 + g;
            #pragma unroll
            for(int n2 = 0; n2 < 8; n2++){
                float o0 = (O[mt][n2][0] + sO[wm][lane][mt*32 + n2*4 + 0])*inv[mt*2];
                float o1 = (O[mt][n2][1] + sO[wm][lane][mt*32 + n2*4 + 1])*inv[mt*2];
                float o2 = (O[mt][n2][2] + sO[wm][lane][mt*32 + n2*4 + 2])*inv[mt*2+1];
                float o3 = (O[mt][n2][3] + sO[wm][lane][mt*32 + n2*4 + 3])*inv[mt*2+1];
                int col = n2*8 + 2*t;
                size_t w0 = ((size_t)(b*TT + row0))*512 + (h*64 + col)/2;
                size_t w1 = ((size_t)(b*TT + row0 + 8))*512 + (h*64 + col)/2;
                uint32_t hh, ll2;
                split2(o0, o1, hh, ll2); g_oh[w0] = hh; g_ol[w0] = ll2;
                split2(o2, o3, hh, ll2); g_oh[w1] = hh; g_ol[w1] = ll2;
            }
        }
    }
}

extern "C" void kernel_launch(void* const* d_in, const int* in_sizes, int n_in,
                              void* d_out, int out_size){
    const float* x         = (const float*)d_in[0];
    const float* summaries = (const float*)d_in[1];
    const float* ctx_w     = (const float*)d_in[2];
    const float* ctx_b     = (const float*)d_in[3];
    const float* base_adj  = (const float*)d_in[4];
    const float* warp_w    = (const float*)d_in[5];
    const float* warp_b    = (const float*)d_in[6];
    const float* gate_w    = (const float*)d_in[7];
    const float* gate_b    = (const float*)d_in[8];
    const float* g1_w      = (const float*)d_in[9];
    const float* g1_b      = (const float*)d_in[10];
    const float* g2_w      = (const float*)d_in[11];
    const float* g2_b      = (const float*)d_in[12];
    const float* ln1_g     = (const float*)d_in[13];
    const float* ln1_b     = (const float*)d_in[14];
    const float* wq        = (const float*)d_in[15];
    const float* bq        = (const float*)d_in[16];
    const float* wk        = (const float*)d_in[17];
    const float* bk        = (const float*)d_in[18];
    const float* wv        = (const float*)d_in[19];
    const float* bv        = (const float*)d_in[20];
    const float* wo        = (const float*)d_in[21];
    const float* bo        = (const float*)d_in[22];
    const float* ln2_g     = (const float*)d_in[23];
    const float* ln2_b     = (const float*)d_in[24];
    const float* ff1_w     = (const float*)d_in[25];
    const float* ff1_b     = (const float*)d_in[26];
    const float* ff2_w     = (const float*)d_in[27];
    const float* ff2_b     = (const float*)d_in[28];
    float* out = (float*)d_out;

    float *p_cur, *p_xo, *p_gate;
    uint32_t *p_oh,*p_ol,*p_nh,*p_nl,*p_mh,*p_ml,*p_wph,*p_wpl;
    cudaGetSymbolAddress((void**)&p_cur,  g_cur);
    cudaGetSymbolAddress((void**)&p_xo,   g_xo);
    cudaGetSymbolAddress((void**)&p_gate, g_gate);
    cudaGetSymbolAddress((void**)&p_oh, g_oh);  cudaGetSymbolAddress((void**)&p_ol, g_ol);
    cudaGetSymbolAddress((void**)&p_nh, g_normh); cudaGetSymbolAddress((void**)&p_nl, g_norml);
    cudaGetSymbolAddress((void**)&p_mh, g_midh); cudaGetSymbolAddress((void**)&p_ml, g_midl);
    cudaGetSymbolAddress((void**)&p_wph, g_wph); cudaGetSymbolAddress((void**)&p_wpl, g_wpl);

    cudaFuncSetAttribute(k_gemm3, cudaFuncAttributeMaxDynamicSharedMemorySize, DSMEM_BYTES);
    cudaFuncSetAttribute(k_qkv,   cudaFuncAttributeMaxDynamicSharedMemorySize, DSMEM_BYTES);

    // ---- router ----
    k_meanT_part<<<dim3(BB,32),256>>>(x);
    k_meanT_reduce<<<BB,256>>>();
    k_ctx<<<dim3(BB,32),128>>>(ctx_w, ctx_b);
    k_route1<<<dim3(BB,80),128>>>(warp_w, summaries, gate_w);
    k_route2<<<1,32>>>(base_adj, warp_b, gate_b,
                       out + BTD, out + BTD + 32, out + BTD + 32 + 256);

    // ---- mega-pack: all 3 hops' weights in ONE launch ----
    k_packall<<<(3*(size_t)WHOP)/256,256>>>(wq, wk, wv, wo, ff1_w, ff2_w);

    // ---- 3 hops ----
    for(int hop = 0; hop < 3; hop++){
        const float* cin = (hop == 0) ? x : p_cur;
        float* cout = (hop == 2) ? out : p_cur;
        uint32_t* wh = p_wph + (size_t)hop*WHOP;
        uint32_t* wl = p_wpl + (size_t)hop*WHOP;

        if(hop > 0){
            k_meanT_part<<<dim3(BB,32),256>>>(cin);
            k_meanT_reduce<<<BB,256>>>();
        }
        k_g1<<<dim3(BB,16),256>>>(g1_w, g1_b, hop);
        k_g2<<<1,256>>>(g2_w, g2_b, hop);
        k_ln2<<<BT,256>>>(cin, ln1_g, ln1_b, hop, p_gate, p_nh, p_nl);
        k_qkv<<<dim3(8,32,3),256,DSMEM_BYTES>>>(p_nh, p_nl, wh, wl, bq, bk, bv, hop);
        k_flash<<<dim3(16,BB*HH),128>>>();
        k_gemm3<<<dim3(8,32),256,DSMEM_BYTES>>>(p_oh,p_ol, wh+3*SZP,wl+3*SZP, bo, DD, hop,
                                    cin, p_gate, nullptr, p_xo, nullptr,nullptr, DD, DD, 0, 0);
        k_ln2<<<BT,256>>>(p_xo, ln2_g, ln2_b, hop, nullptr, p_nh, p_nl);
        k_gemm3<<<dim3(32,32),256,DSMEM_BYTES>>>(p_nh,p_nl, wh+4*SZP,wl+4*SZP, ff1_b, DFF, hop,
                                    nullptr,nullptr,nullptr, nullptr, p_mh,p_ml, DFF, DD, 1, 1);
        k_gemm3<<<dim3(8,32),256,DSMEM_BYTES>>>(p_mh,p_ml, wh+4*SZP+SZF,wl+4*SZP+SZF, ff2_b, DD, hop,
                                    p_xo, nullptr, cin, cout, nullptr,nullptr, DD, DFF, 0, 2);
    }
}